// round 1
// baseline (speedup 1.0000x reference)
#include <cuda_runtime.h>
#include <math.h>

#define BB 16
#define PP 1024
#define KNN 20

// ---------------- scratch (device globals; no allocations allowed) ----------------
__device__ float g_h0[BB * PP * 128];
__device__ float g_x1[BB * PP * 64];
__device__ float g_x2[BB * PP * 64];
__device__ float g_x3[BB * PP * 128];
__device__ float g_x4[BB * PP * 256];
__device__ float g_xc[BB * PP * 512];
__device__ float g_u [BB * PP * 256];
__device__ float g_w [BB * PP * 256];
__device__ float g_pd[BB * PP * PP];        // 64 MB
__device__ int   g_knn[BB * PP * KNN];
__device__ float g_y5[BB * PP * 512];
__device__ float g_feat[BB * 1024];
__device__ float g_sq[BB * PP];

// ---------------- gather: h0[b,p,:] = features[clusters[b,p],:] ----------------
__global__ void gather_kernel(const float* __restrict__ feats, const int* __restrict__ clusters) {
    int t = blockIdx.x * blockDim.x + threadIdx.x;        // over BB*PP*32 float4
    if (t >= BB * PP * 32) return;
    int c4 = t & 31;
    int bp = t >> 5;
    int src = clusters[bp];
    reinterpret_cast<float4*>(g_h0)[(size_t)bp * 32 + c4] =
        reinterpret_cast<const float4*>(feats)[(size_t)src * 32 + c4];
}

// ---------------- squared norms per row ----------------
__global__ void sq_kernel(const float* __restrict__ h, int C) {
    int warp = (blockIdx.x * blockDim.x + threadIdx.x) >> 5;
    int lane = threadIdx.x & 31;
    if (warp >= BB * PP) return;
    const float* row = h + (size_t)warp * C;
    float s = 0.f;
    for (int c = lane; c < C; c += 32) { float v = row[c]; s += v * v; }
    #pragma unroll
    for (int o = 16; o; o >>= 1) s += __shfl_xor_sync(0xffffffffu, s, o);
    if (lane == 0) g_sq[warp] = s;
}

// ---------------- pd = 2*h h^T - sq_i - sq_j   (64x64 tile, 4x4/thread) ----------------
__global__ void pd_kernel(const float* __restrict__ h, int C) {
    __shared__ __align__(16) float As[16][68];
    __shared__ __align__(16) float Bs[16][68];
    int b = blockIdx.z;
    const float* hb = h + (size_t)b * PP * C;
    int rowBase = blockIdx.y * 64, colBase = blockIdx.x * 64;
    int tx = threadIdx.x, ty = threadIdx.y;
    int t = ty * 16 + tx;
    float acc[4][4] = {};
    for (int k0 = 0; k0 < C; k0 += 16) {
        #pragma unroll
        for (int i = 0; i < 4; i++) {
            int e = t + i * 256;
            int r = e >> 4, kk = e & 15;
            As[kk][r] = hb[(size_t)(rowBase + r) * C + k0 + kk];
            Bs[kk][r] = hb[(size_t)(colBase + r) * C + k0 + kk];
        }
        __syncthreads();
        #pragma unroll
        for (int kk = 0; kk < 16; kk++) {
            float4 a  = *reinterpret_cast<const float4*>(&As[kk][ty * 4]);
            float4 bb = *reinterpret_cast<const float4*>(&Bs[kk][tx * 4]);
            float av[4] = {a.x, a.y, a.z, a.w};
            float bv[4] = {bb.x, bb.y, bb.z, bb.w};
            #pragma unroll
            for (int i = 0; i < 4; i++)
                #pragma unroll
                for (int j = 0; j < 4; j++)
                    acc[i][j] += av[i] * bv[j];
        }
        __syncthreads();
    }
    float* pdout = g_pd + (size_t)b * PP * PP;
    const float* sqb = g_sq + b * PP;
    #pragma unroll
    for (int i = 0; i < 4; i++) {
        int r = rowBase + ty * 4 + i;
        float sr = sqb[r];
        #pragma unroll
        for (int j = 0; j < 4; j++) {
            int c = colBase + tx * 4 + j;
            pdout[(size_t)r * PP + c] = 2.f * acc[i][j] - sr - sqb[c];
        }
    }
}

// ---------------- top-20 per row (iterative warp argmax over smem copy) ----------------
__global__ void topk_kernel() {
    __shared__ float srow[8][PP];
    int warp = threadIdx.x >> 5, lane = threadIdx.x & 31;
    int row = blockIdx.x * 8 + warp;
    const float* prow = g_pd + (size_t)row * PP;
    float* s = srow[warp];
    for (int j = lane; j < PP; j += 32) s[j] = prow[j];
    __syncwarp();
    for (int k = 0; k < KNN; k++) {
        float best = -INFINITY; int bi = PP;
        for (int j = lane; j < PP; j += 32) {
            float v = s[j];
            if (v > best) { best = v; bi = j; }   // ascending j: lowest index kept on tie
        }
        #pragma unroll
        for (int o = 16; o; o >>= 1) {
            float ov = __shfl_xor_sync(0xffffffffu, best, o);
            int   oi = __shfl_xor_sync(0xffffffffu, bi, o);
            if (ov > best || (ov == best && oi < bi)) { best = ov; bi = oi; }
        }
        if (lane == 0) g_knn[row * KNN + k] = bi;
        if (lane == (bi & 31)) s[bi] = -INFINITY;
        __syncwarp();
    }
}

// ---------------- dual gemm: u = h*Wa^T, w = h*(Wb-Wa)^T  (W is [O,2C] row-major) ----------------
__global__ void uw_kernel(const float* __restrict__ h, const float* __restrict__ W,
                          int C, int O) {
    __shared__ __align__(16) float Hs [16][68];
    __shared__ __align__(16) float Was[16][68];
    __shared__ __align__(16) float Wbs[16][68];
    int b = blockIdx.z;
    const float* hb = h + (size_t)b * PP * C;
    int rowBase = blockIdx.y * 64, colBase = blockIdx.x * 64;
    int tx = threadIdx.x, ty = threadIdx.y;
    int t = ty * 16 + tx;
    float au[4][4] = {}, aw[4][4] = {};
    int twoC = 2 * C;
    for (int k0 = 0; k0 < C; k0 += 16) {
        #pragma unroll
        for (int i = 0; i < 4; i++) {
            int e = t + i * 256;
            int r = e >> 4, kk = e & 15;
            Hs [kk][r] = hb[(size_t)(rowBase + r) * C + k0 + kk];
            Was[kk][r] = W[(size_t)(colBase + r) * twoC + k0 + kk];
            Wbs[kk][r] = W[(size_t)(colBase + r) * twoC + C + k0 + kk];
        }
        __syncthreads();
        #pragma unroll
        for (int kk = 0; kk < 16; kk++) {
            float4 a  = *reinterpret_cast<const float4*>(&Hs [kk][ty * 4]);
            float4 wa = *reinterpret_cast<const float4*>(&Was[kk][tx * 4]);
            float4 wb = *reinterpret_cast<const float4*>(&Wbs[kk][tx * 4]);
            float av[4] = {a.x, a.y, a.z, a.w};
            float wav[4] = {wa.x, wa.y, wa.z, wa.w};
            float wdv[4] = {wb.x - wa.x, wb.y - wa.y, wb.z - wa.z, wb.w - wa.w};
            #pragma unroll
            for (int i = 0; i < 4; i++)
                #pragma unroll
                for (int j = 0; j < 4; j++) {
                    au[i][j] += av[i] * wav[j];
                    aw[i][j] += av[i] * wdv[j];
                }
        }
        __syncthreads();
    }
    #pragma unroll
    for (int i = 0; i < 4; i++) {
        int p = rowBase + ty * 4 + i;
        size_t base = ((size_t)b * PP + p) * O;
        #pragma unroll
        for (int j = 0; j < 4; j++) {
            int o = colBase + tx * 4 + j;
            g_u[base + o] = au[i][j];
            g_w[base + o] = aw[i][j];
        }
    }
}

// ---------------- aggregate: out[p,o] = max_k lrelu(s*(u[nb]+w[p])+b) ----------------
__global__ void agg_kernel(float* __restrict__ out, const float* __restrict__ s,
                           const float* __restrict__ bias, int O) {
    int o = threadIdx.x;
    int p = blockIdx.x, b = blockIdx.y;
    size_t base = (size_t)b * PP + p;
    float wv = g_w[base * O + o];
    float sv = s[o], bv = bias[o];
    const int* idx = g_knn + base * KNN;
    const float* ub = g_u + (size_t)b * PP * O;
    float m = -INFINITY;
    #pragma unroll 4
    for (int k = 0; k < KNN; k++) {
        int nb = idx[k];
        float y = ub[(size_t)nb * O + o] + wv;
        y = y * sv + bv;
        y = (y > 0.f) ? y : 0.2f * y;
        m = fmaxf(m, y);
    }
    out[base * O + o] = m;
}

// ---------------- concat x1..x4 -> xc [BP,512] ----------------
__global__ void concat_kernel() {
    int t = blockIdx.x * blockDim.x + threadIdx.x;
    if (t >= BB * PP * 512) return;
    int c = t & 511, bp = t >> 9;
    float v;
    if (c < 64)       v = g_x1[(size_t)bp * 64 + c];
    else if (c < 128) v = g_x2[(size_t)bp * 64 + (c - 64)];
    else if (c < 256) v = g_x3[(size_t)bp * 128 + (c - 128)];
    else              v = g_x4[(size_t)bp * 256 + (c - 256)];
    g_xc[t] = v;
}

// ---------------- generic NT gemm + BN + lrelu: out[m,o]=lrelu(s[o]*A[m,:].Wt[o,:]+b[o]) ----------------
__global__ void gemm_bn_kernel(const float* __restrict__ A, const float* __restrict__ Wt,
                               const float* __restrict__ s, const float* __restrict__ bias,
                               float* __restrict__ out, int C, int O) {
    __shared__ __align__(16) float As[16][68];
    __shared__ __align__(16) float Bs[16][68];
    int rowBase = blockIdx.y * 64, colBase = blockIdx.x * 64;
    int tx = threadIdx.x, ty = threadIdx.y;
    int t = ty * 16 + tx;
    float acc[4][4] = {};
    for (int k0 = 0; k0 < C; k0 += 16) {
        #pragma unroll
        for (int i = 0; i < 4; i++) {
            int e = t + i * 256;
            int r = e >> 4, kk = e & 15;
            As[kk][r] = A [(size_t)(rowBase + r) * C + k0 + kk];
            Bs[kk][r] = Wt[(size_t)(colBase + r) * C + k0 + kk];
        }
        __syncthreads();
        #pragma unroll
        for (int kk = 0; kk < 16; kk++) {
            float4 a  = *reinterpret_cast<const float4*>(&As[kk][ty * 4]);
            float4 bb = *reinterpret_cast<const float4*>(&Bs[kk][tx * 4]);
            float av[4] = {a.x, a.y, a.z, a.w};
            float bv[4] = {bb.x, bb.y, bb.z, bb.w};
            #pragma unroll
            for (int i = 0; i < 4; i++)
                #pragma unroll
                for (int j = 0; j < 4; j++)
                    acc[i][j] += av[i] * bv[j];
        }
        __syncthreads();
    }
    #pragma unroll
    for (int i = 0; i < 4; i++) {
        int r = rowBase + ty * 4 + i;
        #pragma unroll
        for (int j = 0; j < 4; j++) {
            int o = colBase + tx * 4 + j;
            float v = acc[i][j] * s[o] + bias[o];
            out[(size_t)r * O + o] = (v > 0.f) ? v : 0.2f * v;
        }
    }
}

// ---------------- pooling: feat[b, 0:512]=max_p y5, feat[b,512:1024]=mean_p y5 ----------------
__global__ void pool_kernel() {
    int b = blockIdx.y;
    int o = blockIdx.x * blockDim.x + threadIdx.x;   // 0..511
    const float* y = g_y5 + (size_t)b * PP * 512;
    float mx = -INFINITY, sm = 0.f;
    for (int p = 0; p < PP; p++) {
        float v = y[(size_t)p * 512 + o];
        mx = fmaxf(mx, v);
        sm += v;
    }
    g_feat[b * 1024 + o] = mx;
    g_feat[b * 1024 + 512 + o] = sm * (1.0f / PP);
}

// ---------------- MLP head per cluster ----------------
__global__ void head_kernel(const float* __restrict__ L1, const float* __restrict__ s6, const float* __restrict__ b6,
                            const float* __restrict__ L2, const float* __restrict__ bl2,
                            const float* __restrict__ s7, const float* __restrict__ b7,
                            const float* __restrict__ L3, const float* __restrict__ bl3,
                            float* __restrict__ out) {
    __shared__ float sf[1024];
    __shared__ float z1[512];
    __shared__ float z2[256];
    int b = blockIdx.x, t = threadIdx.x;   // 512 threads
    sf[t] = g_feat[b * 1024 + t];
    sf[t + 512] = g_feat[b * 1024 + 512 + t];
    __syncthreads();
    {
        float a = 0.f;
        const float* r = L1 + (size_t)t * 1024;
        for (int j = 0; j < 1024; j++) a += sf[j] * r[j];
        a = a * s6[t] + b6[t];
        z1[t] = (a > 0.f) ? a : 0.2f * a;
    }
    __syncthreads();
    if (t < 256) {
        float a = 0.f;
        const float* r = L2 + (size_t)t * 512;
        for (int j = 0; j < 512; j++) a += z1[j] * r[j];
        a = (a + bl2[t]) * s7[t] + b7[t];
        a = (a > 0.f) ? a : 0.2f * a;
        z2[t] = a * L3[t];
    }
    __syncthreads();
    if (t < 128) z2[t] += z2[t + 128];
    __syncthreads();
    if (t < 64) z2[t] += z2[t + 64];
    __syncthreads();
    if (t < 32) {
        float v = z2[t] + z2[t + 32];
        #pragma unroll
        for (int o = 16; o; o >>= 1) v += __shfl_down_sync(0xffffffffu, v, o);
        if (t == 0) {
            float z = v + bl3[0];
            out[b] = 1.0f / (1.0f + expf(-z));
        }
    }
}

// ---------------- host-side orchestration ----------------
static void run_stage(const float* h, int C, int O, const float* W,
                      const float* s, const float* bias, float* xout) {
    sq_kernel<<<(BB * PP * 32 + 255) / 256, 256>>>(h, C);
    dim3 blk(16, 16);
    pd_kernel<<<dim3(PP / 64, PP / 64, BB), blk>>>(h, C);
    topk_kernel<<<BB * PP / 8, 256>>>();
    uw_kernel<<<dim3(O / 64, PP / 64, BB), blk>>>(h, W, C, O);
    agg_kernel<<<dim3(PP, BB), O>>>(xout, s, bias, O);
}

extern "C" void kernel_launch(void* const* d_in, const int* in_sizes, int n_in,
                              void* d_out, int out_size) {
    const int* clusters;
    const float* features;
    if (in_sizes[0] == BB * PP) {          // reference-signature order
        clusters = (const int*)d_in[0];
        features = (const float*)d_in[1];
    } else {                               // setup_inputs dict order
        features = (const float*)d_in[0];
        clusters = (const int*)d_in[1];
    }
    const float* W1  = (const float*)d_in[2];
    const float* s1  = (const float*)d_in[3];
    const float* b1  = (const float*)d_in[4];
    const float* W2  = (const float*)d_in[5];
    const float* s2  = (const float*)d_in[6];
    const float* b2  = (const float*)d_in[7];
    const float* W3  = (const float*)d_in[8];
    const float* s3  = (const float*)d_in[9];
    const float* b3  = (const float*)d_in[10];
    const float* W4  = (const float*)d_in[11];
    const float* s4  = (const float*)d_in[12];
    const float* b4  = (const float*)d_in[13];
    const float* W5  = (const float*)d_in[14];
    const float* s5  = (const float*)d_in[15];
    const float* b5  = (const float*)d_in[16];
    const float* L1  = (const float*)d_in[17];
    const float* s6  = (const float*)d_in[18];
    const float* b6  = (const float*)d_in[19];
    const float* L2  = (const float*)d_in[20];
    const float* bl2 = (const float*)d_in[21];
    const float* s7  = (const float*)d_in[22];
    const float* b7  = (const float*)d_in[23];
    const float* L3  = (const float*)d_in[24];
    const float* bl3 = (const float*)d_in[25];
    float* out = (float*)d_out;

    float *h0, *x1, *x2, *x3, *x4, *xc, *y5;
    cudaGetSymbolAddress((void**)&h0, g_h0);
    cudaGetSymbolAddress((void**)&x1, g_x1);
    cudaGetSymbolAddress((void**)&x2, g_x2);
    cudaGetSymbolAddress((void**)&x3, g_x3);
    cudaGetSymbolAddress((void**)&x4, g_x4);
    cudaGetSymbolAddress((void**)&xc, g_xc);
    cudaGetSymbolAddress((void**)&y5, g_y5);

    gather_kernel<<<(BB * PP * 32 + 255) / 256, 256>>>(features, clusters);

    run_stage(h0, 128, 64,  W1, s1, b1, x1);
    run_stage(x1, 64,  64,  W2, s2, b2, x2);
    run_stage(x2, 64,  128, W3, s3, b3, x3);
    run_stage(x3, 128, 256, W4, s4, b4, x4);

    concat_kernel<<<(BB * PP * 512 + 255) / 256, 256>>>();
    gemm_bn_kernel<<<dim3(512 / 64, BB * PP / 64), dim3(16, 16)>>>(xc, W5, s5, b5, y5, 512, 512);
    pool_kernel<<<dim3(2, BB), 256>>>();
    head_kernel<<<BB, 512>>>(L1, s6, b6, L2, bl2, s7, b7, L3, bl3, out);
}

// round 2
// speedup vs baseline: 1.1091x; 1.1091x over previous
#include <cuda_runtime.h>
#include <math.h>

#define BB 16
#define PP 1024
#define KNN 20

// ---------------- scratch ----------------
__device__ float g_h0[BB * PP * 128];
__device__ float g_xc[BB * PP * 512];      // concat of x1(64) x2(64) x3(128) x4(256)
__device__ float g_uw[BB * PP * 512];      // [u | w], width 2*O (max 512)
__device__ float g_pd[BB * PP * PP];       // 64 MB
__device__ int   g_knn[BB * PP * KNN];
__device__ float g_y5[BB * PP * 512];
__device__ float g_feat[BB * 1024];
__device__ float g_sq[BB * PP];
__device__ float g_wcat[512 * 128];        // [Wa ; Wb-Wa] (2O x C), max 512x128

// ---------------- gather ----------------
__global__ void gather_kernel(const float* __restrict__ feats, const int* __restrict__ clusters) {
    int t = blockIdx.x * blockDim.x + threadIdx.x;
    if (t >= BB * PP * 32) return;
    int c4 = t & 31, bp = t >> 5;
    int src = clusters[bp];
    reinterpret_cast<float4*>(g_h0)[(size_t)bp * 32 + c4] =
        reinterpret_cast<const float4*>(feats)[(size_t)src * 32 + c4];
}

// ---------------- squared norms ----------------
__global__ void sq_kernel(const float* __restrict__ h, int lda, int C) {
    int warp = (blockIdx.x * blockDim.x + threadIdx.x) >> 5;
    int lane = threadIdx.x & 31;
    if (warp >= BB * PP) return;
    const float* row = h + (size_t)warp * lda;
    float s = 0.f;
    for (int c = lane; c < C; c += 32) { float v = row[c]; s += v * v; }
    #pragma unroll
    for (int o = 16; o; o >>= 1) s += __shfl_xor_sync(0xffffffffu, s, o);
    if (lane == 0) g_sq[warp] = s;
}

// ---------------- unified 128x128x8 double-buffered SGEMM (NT) ----------------
// C[m,n] = sum_k A[m,k]*B[n,k]; epilogues: 0 plain, 1 pd, 2 BN+lrelu
#define EPI_PLAIN 0
#define EPI_PD    1
#define EPI_BN    2

__global__ void __launch_bounds__(256, 2)
sgemm_nt(const float* __restrict__ A, int lda, long sA,
         const float* __restrict__ B, int ldb, long sB,
         float* __restrict__ Cout, int ldc, long sC,
         int K,
         const float* __restrict__ sq, long sSq,
         const float* __restrict__ bn_s, const float* __restrict__ bn_b,
         int epi) {
    __shared__ __align__(16) float As[2][8][132];
    __shared__ __align__(16) float Bs[2][8][132];
    int b = blockIdx.z;
    A += (size_t)b * sA; B += (size_t)b * sB; Cout += (size_t)b * sC;
    const float* sqb = sq + (size_t)b * sSq;
    int rowBase = blockIdx.y * 128, colBase = blockIdx.x * 128;

    int tid = threadIdx.x;
    int lr = tid >> 1;            // 0..127 tile row
    int lk = (tid & 1) << 2;      // 0 or 4
    const float* Aptr = A + (size_t)(rowBase + lr) * lda + lk;
    const float* Bptr = B + (size_t)(colBase + lr) * ldb + lk;
    int tx = tid & 15, ty = tid >> 4;

    float acc[8][8] = {};
    float4 ra = *reinterpret_cast<const float4*>(Aptr);
    float4 rb = *reinterpret_cast<const float4*>(Bptr);
    As[0][lk + 0][lr] = ra.x; As[0][lk + 1][lr] = ra.y; As[0][lk + 2][lr] = ra.z; As[0][lk + 3][lr] = ra.w;
    Bs[0][lk + 0][lr] = rb.x; Bs[0][lk + 1][lr] = rb.y; Bs[0][lk + 2][lr] = rb.z; Bs[0][lk + 3][lr] = rb.w;
    __syncthreads();

    int KT = K >> 3;
    int buf = 0;
    for (int kt = 0; kt < KT; kt++) {
        if (kt + 1 < KT) {
            ra = *reinterpret_cast<const float4*>(Aptr + (kt + 1) * 8);
            rb = *reinterpret_cast<const float4*>(Bptr + (kt + 1) * 8);
        }
        #pragma unroll
        for (int k = 0; k < 8; k++) {
            float4 a0 = *reinterpret_cast<const float4*>(&As[buf][k][ty * 4]);
            float4 a1 = *reinterpret_cast<const float4*>(&As[buf][k][ty * 4 + 64]);
            float4 b0 = *reinterpret_cast<const float4*>(&Bs[buf][k][tx * 4]);
            float4 b1 = *reinterpret_cast<const float4*>(&Bs[buf][k][tx * 4 + 64]);
            float av[8] = {a0.x, a0.y, a0.z, a0.w, a1.x, a1.y, a1.z, a1.w};
            float bv[8] = {b0.x, b0.y, b0.z, b0.w, b1.x, b1.y, b1.z, b1.w};
            #pragma unroll
            for (int i = 0; i < 8; i++)
                #pragma unroll
                for (int j = 0; j < 8; j++)
                    acc[i][j] += av[i] * bv[j];
        }
        if (kt + 1 < KT) {
            int nb = buf ^ 1;
            As[nb][lk + 0][lr] = ra.x; As[nb][lk + 1][lr] = ra.y; As[nb][lk + 2][lr] = ra.z; As[nb][lk + 3][lr] = ra.w;
            Bs[nb][lk + 0][lr] = rb.x; Bs[nb][lk + 1][lr] = rb.y; Bs[nb][lk + 2][lr] = rb.z; Bs[nb][lk + 3][lr] = rb.w;
            __syncthreads();
            buf = nb;
        }
    }

    // epilogue
    #pragma unroll
    for (int jj = 0; jj < 2; jj++) {
        int c = colBase + tx * 4 + jj * 64;
        float4 colS, colB, colSq;
        if (epi == EPI_BN) {
            colS = *reinterpret_cast<const float4*>(&bn_s[c]);
            colB = *reinterpret_cast<const float4*>(&bn_b[c]);
        } else if (epi == EPI_PD) {
            colSq = *reinterpret_cast<const float4*>(&sqb[c]);
        }
        #pragma unroll
        for (int ii = 0; ii < 2; ii++) {
            #pragma unroll
            for (int i = 0; i < 4; i++) {
                int r = rowBase + ty * 4 + ii * 64 + i;
                float4 v;
                v.x = acc[ii * 4 + i][jj * 4 + 0];
                v.y = acc[ii * 4 + i][jj * 4 + 1];
                v.z = acc[ii * 4 + i][jj * 4 + 2];
                v.w = acc[ii * 4 + i][jj * 4 + 3];
                if (epi == EPI_PD) {
                    float sr = sqb[r];
                    v.x = 2.f * v.x - sr - colSq.x;
                    v.y = 2.f * v.y - sr - colSq.y;
                    v.z = 2.f * v.z - sr - colSq.z;
                    v.w = 2.f * v.w - sr - colSq.w;
                } else if (epi == EPI_BN) {
                    v.x = v.x * colS.x + colB.x; v.x = (v.x > 0.f) ? v.x : 0.2f * v.x;
                    v.y = v.y * colS.y + colB.y; v.y = (v.y > 0.f) ? v.y : 0.2f * v.y;
                    v.z = v.z * colS.z + colB.z; v.z = (v.z > 0.f) ? v.z : 0.2f * v.z;
                    v.w = v.w * colS.w + colB.w; v.w = (v.w > 0.f) ? v.w : 0.2f * v.w;
                }
                *reinterpret_cast<float4*>(&Cout[(size_t)r * ldc + c]) = v;
            }
        }
    }
}

// ---------------- top-20 per row ----------------
__global__ void topk_kernel() {
    __shared__ float srow[8][PP];
    int warp = threadIdx.x >> 5, lane = threadIdx.x & 31;
    int row = blockIdx.x * 8 + warp;
    const float* prow = g_pd + (size_t)row * PP;
    float* s = srow[warp];
    for (int j = lane; j < PP; j += 32) s[j] = prow[j];
    __syncwarp();
    for (int k = 0; k < KNN; k++) {
        float best = -INFINITY; int bi = PP;
        for (int j = lane; j < PP; j += 32) {
            float v = s[j];
            if (v > best) { best = v; bi = j; }
        }
        #pragma unroll
        for (int o = 16; o; o >>= 1) {
            float ov = __shfl_xor_sync(0xffffffffu, best, o);
            int   oi = __shfl_xor_sync(0xffffffffu, bi, o);
            if (ov > best || (ov == best && oi < bi)) { best = ov; bi = oi; }
        }
        if (lane == 0) g_knn[row * KNN + k] = bi;
        if (lane == (bi & 31)) s[bi] = -INFINITY;
        __syncwarp();
    }
}

// ---------------- weight prep: Wcat = [Wa ; Wb - Wa], (2O x C) ----------------
__global__ void prep_wcat(const float* __restrict__ W, int C, int O) {
    int t = blockIdx.x * blockDim.x + threadIdx.x;
    if (t >= O * C) return;
    int o = t / C, c = t % C;
    float wa = W[(size_t)o * 2 * C + c];
    float wb = W[(size_t)o * 2 * C + C + c];
    g_wcat[(size_t)o * C + c] = wa;
    g_wcat[(size_t)(O + o) * C + c] = wb - wa;
}

// ---------------- aggregate: xc_col[p,o] = max_k lrelu(s*(u[nb]+w[p])+b) ----------------
__global__ void agg_kernel(float* __restrict__ out, const float* __restrict__ uw,
                           const float* __restrict__ s, const float* __restrict__ bias, int O) {
    int o = threadIdx.x;
    int p = blockIdx.x, b = blockIdx.y;
    size_t base = (size_t)b * PP + p;
    int twoO = 2 * O;
    float wv = uw[base * twoO + O + o];
    float sv = s[o], bv = bias[o];
    const int* idx = g_knn + base * KNN;
    const float* ub = uw + (size_t)b * PP * twoO;
    float m = -INFINITY;
    #pragma unroll 4
    for (int k = 0; k < KNN; k++) {
        int nb = idx[k];
        float y = ub[(size_t)nb * twoO + o] + wv;
        y = y * sv + bv;
        y = (y > 0.f) ? y : 0.2f * y;
        m = fmaxf(m, y);
    }
    out[base * 512 + o] = m;
}

// ---------------- pooling ----------------
__global__ void pool_kernel() {
    int b = blockIdx.y;
    int o = blockIdx.x * blockDim.x + threadIdx.x;
    const float* y = g_y5 + (size_t)b * PP * 512;
    float mx = -INFINITY, sm = 0.f;
    for (int p = 0; p < PP; p++) {
        float v = y[(size_t)p * 512 + o];
        mx = fmaxf(mx, v);
        sm += v;
    }
    g_feat[b * 1024 + o] = mx;
    g_feat[b * 1024 + 512 + o] = sm * (1.0f / PP);
}

// ---------------- MLP head ----------------
__global__ void head_kernel(const float* __restrict__ L1, const float* __restrict__ s6, const float* __restrict__ b6,
                            const float* __restrict__ L2, const float* __restrict__ bl2,
                            const float* __restrict__ s7, const float* __restrict__ b7,
                            const float* __restrict__ L3, const float* __restrict__ bl3,
                            float* __restrict__ out) {
    __shared__ float sf[1024];
    __shared__ float z1[512];
    __shared__ float z2[256];
    int b = blockIdx.x, t = threadIdx.x;
    sf[t] = g_feat[b * 1024 + t];
    sf[t + 512] = g_feat[b * 1024 + 512 + t];
    __syncthreads();
    {
        float a = 0.f;
        const float* r = L1 + (size_t)t * 1024;
        for (int j = 0; j < 1024; j++) a += sf[j] * r[j];
        a = a * s6[t] + b6[t];
        z1[t] = (a > 0.f) ? a : 0.2f * a;
    }
    __syncthreads();
    if (t < 256) {
        float a = 0.f;
        const float* r = L2 + (size_t)t * 512;
        for (int j = 0; j < 512; j++) a += z1[j] * r[j];
        a = (a + bl2[t]) * s7[t] + b7[t];
        a = (a > 0.f) ? a : 0.2f * a;
        z2[t] = a * L3[t];
    }
    __syncthreads();
    if (t < 128) z2[t] += z2[t + 128];
    __syncthreads();
    if (t < 64) z2[t] += z2[t + 64];
    __syncthreads();
    if (t < 32) {
        float v = z2[t] + z2[t + 32];
        #pragma unroll
        for (int o = 16; o; o >>= 1) v += __shfl_down_sync(0xffffffffu, v, o);
        if (t == 0) {
            float z = v + bl3[0];
            out[b] = 1.0f / (1.0f + expf(-z));
        }
    }
}

// ---------------- host orchestration ----------------
static void run_stage(const float* h, int lda, int C, int O,
                      const float* W, const float* s, const float* bias,
                      float* xc_col, float* uw, float* pd, float* sq, float* wcat) {
    sq_kernel<<<BB * PP / 8, 256>>>(h, lda, C);
    // pd = 2*h h^T - sq_i - sq_j  (batched over BB)
    sgemm_nt<<<dim3(PP / 128, PP / 128, BB), 256>>>(
        h, lda, (long)PP * lda,
        h, lda, (long)PP * lda,
        pd, PP, (long)PP * PP,
        C, sq, PP, nullptr, nullptr, EPI_PD);
    topk_kernel<<<BB * PP / 8, 256>>>();
    prep_wcat<<<(O * C + 255) / 256, 256>>>(W, C, O);
    // uw = h * Wcat^T  over all BB*PP rows at once
    sgemm_nt<<<dim3((2 * O) / 128, (BB * PP) / 128, 1), 256>>>(
        h, lda, 0,
        wcat, C, 0,
        uw, 2 * O, 0,
        C, nullptr, 0, nullptr, nullptr, EPI_PLAIN);
    agg_kernel<<<dim3(PP, BB), O>>>(xc_col, uw, s, bias, O);
}

extern "C" void kernel_launch(void* const* d_in, const int* in_sizes, int n_in,
                              void* d_out, int out_size) {
    const int* clusters;
    const float* features;
    if (in_sizes[0] == BB * PP) {
        clusters = (const int*)d_in[0];
        features = (const float*)d_in[1];
    } else {
        features = (const float*)d_in[0];
        clusters = (const int*)d_in[1];
    }
    const float* W1  = (const float*)d_in[2];
    const float* s1  = (const float*)d_in[3];
    const float* b1  = (const float*)d_in[4];
    const float* W2  = (const float*)d_in[5];
    const float* s2  = (const float*)d_in[6];
    const float* b2  = (const float*)d_in[7];
    const float* W3  = (const float*)d_in[8];
    const float* s3  = (const float*)d_in[9];
    const float* b3  = (const float*)d_in[10];
    const float* W4  = (const float*)d_in[11];
    const float* s4  = (const float*)d_in[12];
    const float* b4  = (const float*)d_in[13];
    const float* W5  = (const float*)d_in[14];
    const float* s5  = (const float*)d_in[15];
    const float* b5  = (const float*)d_in[16];
    const float* L1  = (const float*)d_in[17];
    const float* s6  = (const float*)d_in[18];
    const float* b6  = (const float*)d_in[19];
    const float* L2  = (const float*)d_in[20];
    const float* bl2 = (const float*)d_in[21];
    const float* s7  = (const float*)d_in[22];
    const float* b7  = (const float*)d_in[23];
    const float* L3  = (const float*)d_in[24];
    const float* bl3 = (const float*)d_in[25];
    float* out = (float*)d_out;

    float *h0, *xc, *uw, *pd, *sq, *wcat, *y5;
    cudaGetSymbolAddress((void**)&h0, g_h0);
    cudaGetSymbolAddress((void**)&xc, g_xc);
    cudaGetSymbolAddress((void**)&uw, g_uw);
    cudaGetSymbolAddress((void**)&pd, g_pd);
    cudaGetSymbolAddress((void**)&sq, g_sq);
    cudaGetSymbolAddress((void**)&wcat, g_wcat);
    cudaGetSymbolAddress((void**)&y5, g_y5);

    gather_kernel<<<(BB * PP * 32 + 255) / 256, 256>>>(features, clusters);

    // EdgeConv stages write directly into xc column slices
    run_stage(h0,       128, 128, 64,  W1, s1, b1, xc + 0,   uw, pd, sq, wcat);
    run_stage(xc + 0,   512, 64,  64,  W2, s2, b2, xc + 64,  uw, pd, sq, wcat);
    run_stage(xc + 64,  512, 64,  128, W3, s3, b3, xc + 128, uw, pd, sq, wcat);
    run_stage(xc + 128, 512, 128, 256, W4, s4, b4, xc + 256, uw, pd, sq, wcat);

    // conv5 + BN + lrelu: y5 = lrelu(s5 * (xc @ W5^T) + b5)
    sgemm_nt<<<dim3(512 / 128, (BB * PP) / 128, 1), 256>>>(
        xc, 512, 0,
        W5, 512, 0,
        y5, 512, 0,
        512, nullptr, 0, s5, b5, EPI_BN);

    pool_kernel<<<dim3(2, BB), 256>>>();
    head_kernel<<<BB, 512>>>(L1, s6, b6, L2, bl2, s7, b7, L3, bl3, out);
}

// round 3
// speedup vs baseline: 1.1619x; 1.0476x over previous
#include <cuda_runtime.h>
#include <math.h>

#define BB 16
#define PP 1024
#define KNN 20

// ---------------- scratch ----------------
__device__ float g_h0[BB * PP * 128];
__device__ float g_xc[BB * PP * 512];      // concat of x1(64) x2(64) x3(128) x4(256)
__device__ float g_uw[BB * PP * 512];      // [u | w], width 2*O (max 512)
__device__ float g_pd[BB * PP * PP];       // 64 MB
__device__ int   g_knn[BB * PP * KNN];
__device__ float g_y5[BB * PP * 512];
__device__ float g_feat[BB * 1024];
__device__ float g_sq[BB * PP];
__device__ float g_wc1[128 * 128];
__device__ float g_wc2[128 * 64];
__device__ float g_wc3[256 * 64];
__device__ float g_wc4[512 * 128];
__device__ float g_pmax[BB * 8 * 512];
__device__ float g_psum[BB * 8 * 512];

// ---------------- gather ----------------
__global__ void gather_kernel(const float* __restrict__ feats, const int* __restrict__ clusters) {
    int t = blockIdx.x * blockDim.x + threadIdx.x;
    if (t >= BB * PP * 32) return;
    int c4 = t & 31, bp = t >> 5;
    int src = clusters[bp];
    reinterpret_cast<float4*>(g_h0)[(size_t)bp * 32 + c4] =
        reinterpret_cast<const float4*>(feats)[(size_t)src * 32 + c4];
}

// ---------------- squared norms (h0 only) ----------------
__global__ void sq_kernel(const float* __restrict__ h, int lda, int C) {
    int warp = (blockIdx.x * blockDim.x + threadIdx.x) >> 5;
    int lane = threadIdx.x & 31;
    if (warp >= BB * PP) return;
    const float* row = h + (size_t)warp * lda;
    float s = 0.f;
    for (int c = lane; c < C; c += 32) { float v = row[c]; s += v * v; }
    #pragma unroll
    for (int o = 16; o; o >>= 1) s += __shfl_xor_sync(0xffffffffu, s, o);
    if (lane == 0) g_sq[warp] = s;
}

// ---------------- unified 128x128x8 double-buffered SGEMM (NT) ----------------
#define EPI_PLAIN 0
#define EPI_PD    1
#define EPI_BN    2

__global__ void __launch_bounds__(256, 2)
sgemm_nt(const float* __restrict__ A, int lda, long sA,
         const float* __restrict__ B, int ldb, long sB,
         float* __restrict__ Cout, int ldc, long sC,
         int K,
         const float* __restrict__ sq, long sSq,
         const float* __restrict__ bn_s, const float* __restrict__ bn_b,
         int epi) {
    __shared__ __align__(16) float As[2][8][132];
    __shared__ __align__(16) float Bs[2][8][132];
    int b = blockIdx.z;
    A += (size_t)b * sA; B += (size_t)b * sB; Cout += (size_t)b * sC;
    const float* sqb = sq + (size_t)b * sSq;
    int rowBase = blockIdx.y * 128, colBase = blockIdx.x * 128;

    int tid = threadIdx.x;
    int lr = tid >> 1;
    int lk = (tid & 1) << 2;
    const float* Aptr = A + (size_t)(rowBase + lr) * lda + lk;
    const float* Bptr = B + (size_t)(colBase + lr) * ldb + lk;
    int tx = tid & 15, ty = tid >> 4;

    float acc[8][8] = {};
    float4 ra = *reinterpret_cast<const float4*>(Aptr);
    float4 rb = *reinterpret_cast<const float4*>(Bptr);
    As[0][lk + 0][lr] = ra.x; As[0][lk + 1][lr] = ra.y; As[0][lk + 2][lr] = ra.z; As[0][lk + 3][lr] = ra.w;
    Bs[0][lk + 0][lr] = rb.x; Bs[0][lk + 1][lr] = rb.y; Bs[0][lk + 2][lr] = rb.z; Bs[0][lk + 3][lr] = rb.w;
    __syncthreads();

    int KT = K >> 3;
    int buf = 0;
    for (int kt = 0; kt < KT; kt++) {
        if (kt + 1 < KT) {
            ra = *reinterpret_cast<const float4*>(Aptr + (kt + 1) * 8);
            rb = *reinterpret_cast<const float4*>(Bptr + (kt + 1) * 8);
        }
        #pragma unroll
        for (int k = 0; k < 8; k++) {
            float4 a0 = *reinterpret_cast<const float4*>(&As[buf][k][ty * 4]);
            float4 a1 = *reinterpret_cast<const float4*>(&As[buf][k][ty * 4 + 64]);
            float4 b0 = *reinterpret_cast<const float4*>(&Bs[buf][k][tx * 4]);
            float4 b1 = *reinterpret_cast<const float4*>(&Bs[buf][k][tx * 4 + 64]);
            float av[8] = {a0.x, a0.y, a0.z, a0.w, a1.x, a1.y, a1.z, a1.w};
            float bv[8] = {b0.x, b0.y, b0.z, b0.w, b1.x, b1.y, b1.z, b1.w};
            #pragma unroll
            for (int i = 0; i < 8; i++)
                #pragma unroll
                for (int j = 0; j < 8; j++)
                    acc[i][j] += av[i] * bv[j];
        }
        if (kt + 1 < KT) {
            int nb = buf ^ 1;
            As[nb][lk + 0][lr] = ra.x; As[nb][lk + 1][lr] = ra.y; As[nb][lk + 2][lr] = ra.z; As[nb][lk + 3][lr] = ra.w;
            Bs[nb][lk + 0][lr] = rb.x; Bs[nb][lk + 1][lr] = rb.y; Bs[nb][lk + 2][lr] = rb.z; Bs[nb][lk + 3][lr] = rb.w;
            __syncthreads();
            buf = nb;
        }
    }

    #pragma unroll
    for (int jj = 0; jj < 2; jj++) {
        int c = colBase + tx * 4 + jj * 64;
        float4 colS, colB, colSq;
        if (epi == EPI_BN) {
            colS = *reinterpret_cast<const float4*>(&bn_s[c]);
            colB = *reinterpret_cast<const float4*>(&bn_b[c]);
        } else if (epi == EPI_PD) {
            colSq = *reinterpret_cast<const float4*>(&sqb[c]);
        }
        #pragma unroll
        for (int ii = 0; ii < 2; ii++) {
            #pragma unroll
            for (int i = 0; i < 4; i++) {
                int r = rowBase + ty * 4 + ii * 64 + i;
                float4 v;
                v.x = acc[ii * 4 + i][jj * 4 + 0];
                v.y = acc[ii * 4 + i][jj * 4 + 1];
                v.z = acc[ii * 4 + i][jj * 4 + 2];
                v.w = acc[ii * 4 + i][jj * 4 + 3];
                if (epi == EPI_PD) {
                    float sr = sqb[r];
                    v.x = 2.f * v.x - sr - colSq.x;
                    v.y = 2.f * v.y - sr - colSq.y;
                    v.z = 2.f * v.z - sr - colSq.z;
                    v.w = 2.f * v.w - sr - colSq.w;
                } else if (epi == EPI_BN) {
                    v.x = v.x * colS.x + colB.x; v.x = (v.x > 0.f) ? v.x : 0.2f * v.x;
                    v.y = v.y * colS.y + colB.y; v.y = (v.y > 0.f) ? v.y : 0.2f * v.y;
                    v.z = v.z * colS.z + colB.z; v.z = (v.z > 0.f) ? v.z : 0.2f * v.z;
                    v.w = v.w * colS.w + colB.w; v.w = (v.w > 0.f) ? v.w : 0.2f * v.w;
                }
                *reinterpret_cast<float4*>(&Cout[(size_t)r * ldc + c]) = v;
            }
        }
    }
}

// ---------------- top-20 per row: cached per-lane top-2 + rare rescan ----------------
__global__ void __launch_bounds__(256) topk_kernel() {
    int warp = threadIdx.x >> 5, lane = threadIdx.x & 31;
    int row = blockIdx.x * 8 + warp;
    const float* __restrict__ prow = g_pd + (size_t)row * PP;

    // initial per-lane top-2 over 32 strided values (j = slot*32 + lane)
    float m1 = -INFINITY, m2 = -INFINITY;
    int i1 = PP, i2 = PP;
    #pragma unroll
    for (int slot = 0; slot < 32; slot++) {
        int j = slot * 32 + lane;
        float v = __ldg(&prow[j]);
        if (v > m1) { m2 = m1; i2 = i1; m1 = v; i1 = j; }
        else if (v > m2) { m2 = v; i2 = j; }
    }
    bool have2 = true;
    unsigned mask = 0;   // bit per extracted slot of this lane

    for (int k = 0; k < KNN; k++) {
        float best = m1; int bi = i1;
        #pragma unroll
        for (int o = 16; o; o >>= 1) {
            float ov = __shfl_xor_sync(0xffffffffu, best, o);
            int   oi = __shfl_xor_sync(0xffffffffu, bi, o);
            if (ov > best || (ov == best && oi < bi)) { best = ov; bi = oi; }
        }
        if (lane == 0) g_knn[row * KNN + k] = bi;
        if (i1 == bi) {                     // this lane owned the extracted value
            mask |= 1u << (bi >> 5);
            if (have2) { m1 = m2; i1 = i2; have2 = false; }
            else {
                m1 = -INFINITY; m2 = -INFINITY; i1 = PP; i2 = PP;
                #pragma unroll
                for (int slot = 0; slot < 32; slot++) {
                    if (!(mask & (1u << slot))) {
                        int j = slot * 32 + lane;
                        float v = __ldg(&prow[j]);
                        if (v > m1) { m2 = m1; i2 = i1; m1 = v; i1 = j; }
                        else if (v > m2) { m2 = v; i2 = j; }
                    }
                }
                have2 = true;
            }
        }
    }
}

// ---------------- weight prep ----------------
__global__ void prep_wcat(const float* __restrict__ W, float* __restrict__ wcat, int C, int O) {
    int t = blockIdx.x * blockDim.x + threadIdx.x;
    if (t >= O * C) return;
    int o = t / C, c = t % C;
    float wa = W[(size_t)o * 2 * C + c];
    float wb = W[(size_t)o * 2 * C + C + c];
    wcat[(size_t)o * C + c] = wa;
    wcat[(size_t)(O + o) * C + c] = wb - wa;
}

// ---------------- aggregate + fused next-stage sq ----------------
// out[p, o] = max_k lrelu(s*(u[nb]+w[p])+b); sqout[bp] = sum_o out^2
__global__ void __launch_bounds__(256) agg_kernel(
    float* __restrict__ out, const float* __restrict__ uw,
    const float* __restrict__ s, const float* __restrict__ bias,
    int O, float* __restrict__ sqout) {
    __shared__ int sidx[128];        // up to G*KNN = 4*20
    __shared__ float red[256];
    int tid = threadIdx.x;
    int G = 256 / O;
    int pi = tid / O;
    int o = tid - pi * O;
    int b = blockIdx.y;
    int p = blockIdx.x * G + pi;
    size_t base = (size_t)b * PP + p;

    if (tid < G * KNN) {
        int gp = tid / KNN, kk = tid - gp * KNN;
        sidx[tid] = g_knn[((size_t)b * PP + blockIdx.x * G + gp) * KNN + kk];
    }
    __syncthreads();

    int twoO = 2 * O;
    const float* __restrict__ ub = uw + (size_t)b * PP * twoO;
    float wv = __ldg(&ub[(size_t)p * twoO + O + o]);
    float sv = s[o], bv = bias[o];
    const int* idx = sidx + pi * KNN;
    float m = -INFINITY;
    #pragma unroll
    for (int k = 0; k < KNN; k++) {
        int nb = idx[k];
        float y = __ldg(&ub[(size_t)nb * twoO + o]) + wv;
        y = y * sv + bv;
        y = (y > 0.f) ? y : 0.2f * y;
        m = fmaxf(m, y);
    }
    out[base * 512 + o] = m;

    red[tid] = m * m;
    __syncthreads();
    for (int st = O >> 1; st > 0; st >>= 1) {
        if (o < st) red[tid] += red[tid + st];
        __syncthreads();
    }
    if (o == 0) sqout[base] = red[tid];
}

// ---------------- pooling (two-phase) ----------------
__global__ void pool1_kernel() {
    int chunk = blockIdx.x, b = blockIdx.y, o = threadIdx.x;   // 512 threads
    const float* y = g_y5 + (size_t)b * PP * 512 + (size_t)chunk * 128 * 512;
    float mx = -INFINITY, sm = 0.f;
    for (int p = 0; p < 128; p++) {
        float v = y[(size_t)p * 512 + o];
        mx = fmaxf(mx, v);
        sm += v;
    }
    g_pmax[(b * 8 + chunk) * 512 + o] = mx;
    g_psum[(b * 8 + chunk) * 512 + o] = sm;
}

__global__ void pool2_kernel() {
    int b = blockIdx.x, o = threadIdx.x;   // 512 threads
    float mx = -INFINITY, sm = 0.f;
    #pragma unroll
    for (int c = 0; c < 8; c++) {
        mx = fmaxf(mx, g_pmax[(b * 8 + c) * 512 + o]);
        sm += g_psum[(b * 8 + c) * 512 + o];
    }
    g_feat[b * 1024 + o] = mx;
    g_feat[b * 1024 + 512 + o] = sm * (1.0f / PP);
}

// ---------------- MLP head ----------------
__global__ void head_kernel(const float* __restrict__ L1, const float* __restrict__ s6, const float* __restrict__ b6,
                            const float* __restrict__ L2, const float* __restrict__ bl2,
                            const float* __restrict__ s7, const float* __restrict__ b7,
                            const float* __restrict__ L3, const float* __restrict__ bl3,
                            float* __restrict__ out) {
    __shared__ float sf[1024];
    __shared__ float z1[512];
    __shared__ float z2[256];
    int b = blockIdx.x, t = threadIdx.x;
    sf[t] = g_feat[b * 1024 + t];
    sf[t + 512] = g_feat[b * 1024 + 512 + t];
    __syncthreads();
    {
        float a = 0.f;
        const float* r = L1 + (size_t)t * 1024;
        for (int j = 0; j < 1024; j++) a += sf[j] * r[j];
        a = a * s6[t] + b6[t];
        z1[t] = (a > 0.f) ? a : 0.2f * a;
    }
    __syncthreads();
    if (t < 256) {
        float a = 0.f;
        const float* r = L2 + (size_t)t * 512;
        for (int j = 0; j < 512; j++) a += z1[j] * r[j];
        a = (a + bl2[t]) * s7[t] + b7[t];
        a = (a > 0.f) ? a : 0.2f * a;
        z2[t] = a * L3[t];
    }
    __syncthreads();
    if (t < 128) z2[t] += z2[t + 128];
    __syncthreads();
    if (t < 64) z2[t] += z2[t + 64];
    __syncthreads();
    if (t < 32) {
        float v = z2[t] + z2[t + 32];
        #pragma unroll
        for (int o = 16; o; o >>= 1) v += __shfl_down_sync(0xffffffffu, v, o);
        if (t == 0) {
            float z = v + bl3[0];
            out[b] = 1.0f / (1.0f + expf(-z));
        }
    }
}

// ---------------- host orchestration ----------------
static void run_stage(const float* h, int lda, int C, int O,
                      const float* wcat, const float* s, const float* bias,
                      float* xc_col, float* uw, float* pd, float* sq) {
    sgemm_nt<<<dim3(PP / 128, PP / 128, BB), 256>>>(
        h, lda, (long)PP * lda,
        h, lda, (long)PP * lda,
        pd, PP, (long)PP * PP,
        C, sq, PP, nullptr, nullptr, EPI_PD);
    topk_kernel<<<BB * PP / 8, 256>>>();
    sgemm_nt<<<dim3((2 * O) / 128, (BB * PP) / 128, 1), 256>>>(
        h, lda, 0,
        wcat, C, 0,
        uw, 2 * O, 0,
        C, nullptr, 0, nullptr, nullptr, EPI_PLAIN);
    int G = 256 / O;
    agg_kernel<<<dim3(PP / G, BB), 256>>>(xc_col, uw, s, bias, O, sq);
}

extern "C" void kernel_launch(void* const* d_in, const int* in_sizes, int n_in,
                              void* d_out, int out_size) {
    const int* clusters;
    const float* features;
    if (in_sizes[0] == BB * PP) {
        clusters = (const int*)d_in[0];
        features = (const float*)d_in[1];
    } else {
        features = (const float*)d_in[0];
        clusters = (const int*)d_in[1];
    }
    const float* W1  = (const float*)d_in[2];
    const float* s1  = (const float*)d_in[3];
    const float* b1  = (const float*)d_in[4];
    const float* W2  = (const float*)d_in[5];
    const float* s2  = (const float*)d_in[6];
    const float* b2  = (const float*)d_in[7];
    const float* W3  = (const float*)d_in[8];
    const float* s3  = (const float*)d_in[9];
    const float* b3  = (const float*)d_in[10];
    const float* W4  = (const float*)d_in[11];
    const float* s4  = (const float*)d_in[12];
    const float* b4  = (const float*)d_in[13];
    const float* W5  = (const float*)d_in[14];
    const float* s5  = (const float*)d_in[15];
    const float* b5  = (const float*)d_in[16];
    const float* L1  = (const float*)d_in[17];
    const float* s6  = (const float*)d_in[18];
    const float* b6  = (const float*)d_in[19];
    const float* L2  = (const float*)d_in[20];
    const float* bl2 = (const float*)d_in[21];
    const float* s7  = (const float*)d_in[22];
    const float* b7  = (const float*)d_in[23];
    const float* L3  = (const float*)d_in[24];
    const float* bl3 = (const float*)d_in[25];
    float* out = (float*)d_out;

    float *h0, *xc, *uw, *pd, *sq, *y5, *wc1, *wc2, *wc3, *wc4;
    cudaGetSymbolAddress((void**)&h0, g_h0);
    cudaGetSymbolAddress((void**)&xc, g_xc);
    cudaGetSymbolAddress((void**)&uw, g_uw);
    cudaGetSymbolAddress((void**)&pd, g_pd);
    cudaGetSymbolAddress((void**)&sq, g_sq);
    cudaGetSymbolAddress((void**)&y5, g_y5);
    cudaGetSymbolAddress((void**)&wc1, g_wc1);
    cudaGetSymbolAddress((void**)&wc2, g_wc2);
    cudaGetSymbolAddress((void**)&wc3, g_wc3);
    cudaGetSymbolAddress((void**)&wc4, g_wc4);

    gather_kernel<<<(BB * PP * 32 + 255) / 256, 256>>>(features, clusters);
    sq_kernel<<<BB * PP / 8, 256>>>(h0, 128, 128);
    prep_wcat<<<(64  * 128 + 255) / 256, 256>>>(W1, wc1, 128, 64);
    prep_wcat<<<(64  * 64  + 255) / 256, 256>>>(W2, wc2, 64,  64);
    prep_wcat<<<(128 * 64  + 255) / 256, 256>>>(W3, wc3, 64,  128);
    prep_wcat<<<(256 * 128 + 255) / 256, 256>>>(W4, wc4, 128, 256);

    run_stage(h0,       128, 128, 64,  wc1, s1, b1, xc + 0,   uw, pd, sq);
    run_stage(xc + 0,   512, 64,  64,  wc2, s2, b2, xc + 64,  uw, pd, sq);
    run_stage(xc + 64,  512, 64,  128, wc3, s3, b3, xc + 128, uw, pd, sq);
    run_stage(xc + 128, 512, 128, 256, wc4, s4, b4, xc + 256, uw, pd, sq);

    sgemm_nt<<<dim3(512 / 128, (BB * PP) / 128, 1), 256>>>(
        xc, 512, 0,
        W5, 512, 0,
        y5, 512, 0,
        512, nullptr, 0, s5, b5, EPI_BN);

    pool1_kernel<<<dim3(8, BB), 512>>>();
    pool2_kernel<<<BB, 512>>>();
    head_kernel<<<BB, 512>>>(L1, s6, b6, L2, bl2, s7, b7, L3, bl3, out);
}

// round 5
// speedup vs baseline: 1.4522x; 1.2499x over previous
#include <cuda_runtime.h>
#include <cuda_bf16.h>
#include <math.h>
#include <stdint.h>

#define BB 16
#define PP 1024
#define KNN 20

// ---------------- scratch ----------------
__device__ float g_h0[BB * PP * 128];                 // fp32 (for sq)
__device__ __nv_bfloat16 g_h0h[BB * PP * 128];
__device__ __nv_bfloat16 g_h0l[BB * PP * 128];
__device__ __nv_bfloat16 g_xch[BB * PP * 512];        // bf16 hi of concat features
__device__ __nv_bfloat16 g_xcl[BB * PP * 512];        // bf16 lo
__device__ float g_uw[BB * PP * 512];
__device__ float g_pd[BB * PP * PP];                  // 64 MB
__device__ int   g_knn[BB * PP * KNN];
__device__ float g_y5[BB * PP * 512];
__device__ float g_feat[BB * 1024];
__device__ float g_sq[BB * PP];
__device__ float g_pmax[BB * 8 * 512];
__device__ float g_psum[BB * 8 * 512];
// bf16 weights: wcat = [Wa ; Wb-Wa] (2O x C), W5 (512x512)
__device__ __nv_bfloat16 g_w1h[128 * 128], g_w1l[128 * 128];
__device__ __nv_bfloat16 g_w2h[128 * 64],  g_w2l[128 * 64];
__device__ __nv_bfloat16 g_w3h[256 * 64],  g_w3l[256 * 64];
__device__ __nv_bfloat16 g_w4h[512 * 128], g_w4l[512 * 128];
__device__ __nv_bfloat16 g_w5h[512 * 512], g_w5l[512 * 512];

__device__ __forceinline__ void bsplit(float x, __nv_bfloat16& hi, __nv_bfloat16& lo) {
    hi = __float2bfloat16(x);
    lo = __float2bfloat16(x - __bfloat162float(hi));
}

__device__ __forceinline__ uint32_t smem_u32(const void* p) {
    uint32_t a;
    asm("{ .reg .u64 t; cvta.to.shared.u64 t, %1; cvt.u32.u64 %0, t; }" : "=r"(a) : "l"(p));
    return a;
}

__device__ __forceinline__ void cp_async16(uint32_t dst, const void* src) {
    asm volatile("cp.async.ca.shared.global [%0], [%1], 16;"
                 :: "r"(dst), "l"(__cvta_generic_to_global(src)));
}
#define CP_COMMIT() asm volatile("cp.async.commit_group;")

__device__ __forceinline__ void mma16816(float* c, const uint32_t* a, const uint32_t* b) {
    asm volatile(
        "mma.sync.aligned.m16n8k16.row.col.f32.bf16.bf16.f32 "
        "{%0,%1,%2,%3}, {%4,%5,%6,%7}, {%8,%9}, {%0,%1,%2,%3};"
        : "+f"(c[0]), "+f"(c[1]), "+f"(c[2]), "+f"(c[3])
        : "r"(a[0]), "r"(a[1]), "r"(a[2]), "r"(a[3]), "r"(b[0]), "r"(b[1]));
}

// ---------------- gather: h0 fp32 + bf16 hi/lo ----------------
__global__ void gather_kernel(const float* __restrict__ feats, const int* __restrict__ clusters) {
    int t = blockIdx.x * blockDim.x + threadIdx.x;
    if (t >= BB * PP * 32) return;
    int c4 = t & 31, bp = t >> 5;
    int src = clusters[bp];
    float4 v = reinterpret_cast<const float4*>(feats)[(size_t)src * 32 + c4];
    reinterpret_cast<float4*>(g_h0)[(size_t)bp * 32 + c4] = v;
    size_t e = (size_t)bp * 128 + c4 * 4;
    bsplit(v.x, g_h0h[e + 0], g_h0l[e + 0]);
    bsplit(v.y, g_h0h[e + 1], g_h0l[e + 1]);
    bsplit(v.z, g_h0h[e + 2], g_h0l[e + 2]);
    bsplit(v.w, g_h0h[e + 3], g_h0l[e + 3]);
}

// ---------------- squared norms (stage 1) ----------------
__global__ void sq_kernel(const float* __restrict__ h, int lda, int C) {
    int warp = (blockIdx.x * blockDim.x + threadIdx.x) >> 5;
    int lane = threadIdx.x & 31;
    if (warp >= BB * PP) return;
    const float* row = h + (size_t)warp * lda;
    float s = 0.f;
    for (int c = lane; c < C; c += 32) { float v = row[c]; s += v * v; }
    #pragma unroll
    for (int o = 16; o; o >>= 1) s += __shfl_xor_sync(0xffffffffu, s, o);
    if (lane == 0) g_sq[warp] = s;
}

// ---------------- merged weight prep ----------------
__global__ void prep_kernel(const float* __restrict__ W1, const float* __restrict__ W2,
                            const float* __restrict__ W3, const float* __restrict__ W4,
                            const float* __restrict__ W5) {
    int t = blockIdx.x * blockDim.x + threadIdx.x;
    if (t < 8192) {
        int o = t / 128, c = t % 128;
        float wa = W1[(size_t)o * 256 + c], wb = W1[(size_t)o * 256 + 128 + c];
        bsplit(wa, g_w1h[o * 128 + c], g_w1l[o * 128 + c]);
        bsplit(wb - wa, g_w1h[(64 + o) * 128 + c], g_w1l[(64 + o) * 128 + c]);
        return;
    }
    t -= 8192;
    if (t < 4096) {
        int o = t / 64, c = t % 64;
        float wa = W2[(size_t)o * 128 + c], wb = W2[(size_t)o * 128 + 64 + c];
        bsplit(wa, g_w2h[o * 64 + c], g_w2l[o * 64 + c]);
        bsplit(wb - wa, g_w2h[(64 + o) * 64 + c], g_w2l[(64 + o) * 64 + c]);
        return;
    }
    t -= 4096;
    if (t < 8192) {
        int o = t / 64, c = t % 64;
        float wa = W3[(size_t)o * 128 + c], wb = W3[(size_t)o * 128 + 64 + c];
        bsplit(wa, g_w3h[o * 64 + c], g_w3l[o * 64 + c]);
        bsplit(wb - wa, g_w3h[(128 + o) * 64 + c], g_w3l[(128 + o) * 64 + c]);
        return;
    }
    t -= 8192;
    if (t < 32768) {
        int o = t / 128, c = t % 128;
        float wa = W4[(size_t)o * 256 + c], wb = W4[(size_t)o * 256 + 128 + c];
        bsplit(wa, g_w4h[o * 128 + c], g_w4l[o * 128 + c]);
        bsplit(wb - wa, g_w4h[(256 + o) * 128 + c], g_w4l[(256 + o) * 128 + c]);
        return;
    }
    t -= 32768;
    if (t < 262144) {
        bsplit(W5[t], g_w5h[t], g_w5l[t]);
    }
}

// ---------------- mma.sync split-bf16 GEMM: C = A*B^T (NT), tiles 128x128, K step 32 ----------------
#define EPI_PLAIN 0
#define EPI_PD    1
#define EPI_BN    2

#define STRIDE_W 20                 // uint32 words per smem row (80 bytes)
#define TILE_BYTES (128 * STRIDE_W * 4)

__global__ void __launch_bounds__(256)
mmagemm(const __nv_bfloat16* __restrict__ Ahi, const __nv_bfloat16* __restrict__ Alo,
        int lda, long sA, int acoff,
        const __nv_bfloat16* __restrict__ Bhi, const __nv_bfloat16* __restrict__ Blo,
        int ldb, long sB, int bcoff,
        float* __restrict__ Cout, int ldc, long sC,
        int K,
        const float* __restrict__ sq, long sSq,
        const float* __restrict__ bn_s, const float* __restrict__ bn_b, int epi) {
    extern __shared__ char dsm[];
    uint32_t smem_base = smem_u32(dsm);
    int tid = threadIdx.x;
    int lane = tid & 31, wid = tid >> 5;
    int warp_m = wid & 3, warp_n = wid >> 2;
    int g = lane >> 2, tid4 = lane & 3;
    int b = blockIdx.z;
    Ahi += (size_t)b * sA; Alo += (size_t)b * sA;
    Bhi += (size_t)b * sB; Blo += (size_t)b * sB;
    Cout += (size_t)b * sC;
    const float* sqb = sq + (size_t)b * sSq;

    size_t aRow = (size_t)blockIdx.y * 128;
    size_t bRow = (size_t)blockIdx.x * 128;
    int nKb = K >> 5;

    float acc[2][8][4];
    #pragma unroll
    for (int mf = 0; mf < 2; mf++)
        #pragma unroll
        for (int nf = 0; nf < 8; nf++)
            #pragma unroll
            for (int i = 0; i < 4; i++) acc[mf][nf][i] = 0.f;

    // cp.async loader: 4 tiles * 128 rows * 4 chunks(16B) = 2048 chunks, 8 per thread
    auto load_block = [&](int buf, int kb) {
        uint32_t sbuf = smem_base + buf * 4 * TILE_BYTES;
        #pragma unroll
        for (int it = 0; it < 8; it++) {
            int i = tid + it * 256;
            int tile = i >> 9;
            int rem = i & 511;
            int row = rem >> 2;
            int chunk = rem & 3;
            uint32_t dst = sbuf + tile * TILE_BYTES + row * (STRIDE_W * 4) + chunk * 16;
            const __nv_bfloat16* src;
            if (tile == 0)      src = Ahi + (aRow + row) * lda + acoff + kb * 32 + chunk * 8;
            else if (tile == 1) src = Alo + (aRow + row) * lda + acoff + kb * 32 + chunk * 8;
            else if (tile == 2) src = Bhi + (bRow + row) * ldb + bcoff + kb * 32 + chunk * 8;
            else                src = Blo + (bRow + row) * ldb + bcoff + kb * 32 + chunk * 8;
            cp_async16(dst, src);
        }
        CP_COMMIT();
    };

    load_block(0, 0);
    int buf = 0;
    for (int kb = 0; kb < nKb; kb++) {
        bool pref = (kb + 1 < nKb);
        if (pref) load_block(buf ^ 1, kb + 1);
        if (pref) asm volatile("cp.async.wait_group 1;");
        else      asm volatile("cp.async.wait_group 0;");
        __syncthreads();

        const uint32_t* sAh = (const uint32_t*)(dsm + buf * 4 * TILE_BYTES);
        const uint32_t* sAl = sAh + (TILE_BYTES / 4);
        const uint32_t* sBh = sAh + 2 * (TILE_BYTES / 4);
        const uint32_t* sBl = sAh + 3 * (TILE_BYTES / 4);

        #pragma unroll
        for (int s = 0; s < 2; s++) {
            int pk0 = s * 8;
            uint32_t ah[2][4], al[2][4];
            #pragma unroll
            for (int mf = 0; mf < 2; mf++) {
                int R = warp_m * 32 + mf * 16;
                int base0 = (R + g) * STRIDE_W + pk0 + tid4;
                int base1 = (R + g + 8) * STRIDE_W + pk0 + tid4;
                ah[mf][0] = sAh[base0]; ah[mf][1] = sAh[base1];
                ah[mf][2] = sAh[base0 + 4]; ah[mf][3] = sAh[base1 + 4];
                al[mf][0] = sAl[base0]; al[mf][1] = sAl[base1];
                al[mf][2] = sAl[base0 + 4]; al[mf][3] = sAl[base1 + 4];
            }
            #pragma unroll
            for (int nf = 0; nf < 8; nf++) {
                int NR = warp_n * 64 + nf * 8 + g;
                int nb = NR * STRIDE_W + pk0 + tid4;
                uint32_t bh[2], bl[2];
                bh[0] = sBh[nb]; bh[1] = sBh[nb + 4];
                bl[0] = sBl[nb]; bl[1] = sBl[nb + 4];
                #pragma unroll
                for (int mf = 0; mf < 2; mf++) {
                    mma16816(acc[mf][nf], ah[mf], bh);
                    mma16816(acc[mf][nf], al[mf], bh);
                    mma16816(acc[mf][nf], ah[mf], bl);
                }
            }
        }
        __syncthreads();
        buf ^= 1;
    }

    // epilogue: each thread owns rows (r0, r0+8) per mfrag, col pairs per nfrag
    #pragma unroll
    for (int mf = 0; mf < 2; mf++) {
        size_t r0 = aRow + warp_m * 32 + mf * 16 + g;
        size_t r1 = r0 + 8;
        float sr0 = 0.f, sr1 = 0.f;
        if (epi == EPI_PD) { sr0 = sqb[r0]; sr1 = sqb[r1]; }
        #pragma unroll
        for (int nf = 0; nf < 8; nf++) {
            size_t c = (size_t)blockIdx.x * 128 + warp_n * 64 + nf * 8 + 2 * tid4;
            float v0 = acc[mf][nf][0], v1 = acc[mf][nf][1];
            float v2 = acc[mf][nf][2], v3 = acc[mf][nf][3];
            if (epi == EPI_PD) {
                float2 cs = *reinterpret_cast<const float2*>(&sqb[c]);
                v0 = 2.f * v0 - sr0 - cs.x;
                v1 = 2.f * v1 - sr0 - cs.y;
                v2 = 2.f * v2 - sr1 - cs.x;
                v3 = 2.f * v3 - sr1 - cs.y;
            } else if (epi == EPI_BN) {
                float2 cs = *reinterpret_cast<const float2*>(&bn_s[c]);
                float2 cb = *reinterpret_cast<const float2*>(&bn_b[c]);
                v0 = v0 * cs.x + cb.x; v0 = (v0 > 0.f) ? v0 : 0.2f * v0;
                v1 = v1 * cs.y + cb.y; v1 = (v1 > 0.f) ? v1 : 0.2f * v1;
                v2 = v2 * cs.x + cb.x; v2 = (v2 > 0.f) ? v2 : 0.2f * v2;
                v3 = v3 * cs.y + cb.y; v3 = (v3 > 0.f) ? v3 : 0.2f * v3;
            }
            *reinterpret_cast<float2*>(&Cout[r0 * ldc + c]) = make_float2(v0, v1);
            *reinterpret_cast<float2*>(&Cout[r1 * ldc + c]) = make_float2(v2, v3);
        }
    }
}

// ---------------- top-20 per row ----------------
__global__ void __launch_bounds__(256) topk_kernel() {
    int warp = threadIdx.x >> 5, lane = threadIdx.x & 31;
    int row = blockIdx.x * 8 + warp;
    const float* __restrict__ prow = g_pd + (size_t)row * PP;

    float m1 = -INFINITY, m2 = -INFINITY;
    int i1 = PP, i2 = PP;
    #pragma unroll
    for (int slot = 0; slot < 32; slot++) {
        int j = slot * 32 + lane;
        float v = __ldg(&prow[j]);
        if (v > m1) { m2 = m1; i2 = i1; m1 = v; i1 = j; }
        else if (v > m2) { m2 = v; i2 = j; }
    }
    bool have2 = true;
    unsigned mask = 0;

    for (int k = 0; k < KNN; k++) {
        float best = m1; int bi = i1;
        #pragma unroll
        for (int o = 16; o; o >>= 1) {
            float ov = __shfl_xor_sync(0xffffffffu, best, o);
            int   oi = __shfl_xor_sync(0xffffffffu, bi, o);
            if (ov > best || (ov == best && oi < bi)) { best = ov; bi = oi; }
        }
        if (lane == 0) g_knn[row * KNN + k] = bi;
        if (i1 == bi) {
            mask |= 1u << (bi >> 5);
            if (have2) { m1 = m2; i1 = i2; have2 = false; }
            else {
                m1 = -INFINITY; m2 = -INFINITY; i1 = PP; i2 = PP;
                #pragma unroll
                for (int slot = 0; slot < 32; slot++) {
                    if (!(mask & (1u << slot))) {
                        int j = slot * 32 + lane;
                        float v = __ldg(&prow[j]);
                        if (v > m1) { m2 = m1; i2 = i1; m1 = v; i1 = j; }
                        else if (v > m2) { m2 = v; i2 = j; }
                    }
                }
                have2 = true;
            }
        }
    }
}

// ---------------- aggregate + fused next-stage sq + bf16 split output ----------------
__global__ void __launch_bounds__(256) agg_kernel(
    const float* __restrict__ uw,
    const float* __restrict__ s, const float* __restrict__ bias,
    int O, int coloff, float* __restrict__ sqout) {
    __shared__ int sidx[128];
    __shared__ float red[256];
    int tid = threadIdx.x;
    int G = 256 / O;
    int pi = tid / O;
    int o = tid - pi * O;
    int b = blockIdx.y;
    int p = blockIdx.x * G + pi;
    size_t base = (size_t)b * PP + p;

    if (tid < G * KNN) {
        int gp = tid / KNN, kk = tid - gp * KNN;
        sidx[tid] = g_knn[((size_t)b * PP + blockIdx.x * G + gp) * KNN + kk];
    }
    __syncthreads();

    int twoO = 2 * O;
    const float* __restrict__ ub = uw + (size_t)b * PP * twoO;
    float wv = __ldg(&ub[(size_t)p * twoO + O + o]);
    float sv = s[o], bv = bias[o];
    const int* idx = sidx + pi * KNN;
    float m = -INFINITY;
    #pragma unroll
    for (int k = 0; k < KNN; k++) {
        int nb = idx[k];
        float y = __ldg(&ub[(size_t)nb * twoO + o]) + wv;
        y = y * sv + bv;
        y = (y > 0.f) ? y : 0.2f * y;
        m = fmaxf(m, y);
    }
    bsplit(m, g_xch[base * 512 + coloff + o], g_xcl[base * 512 + coloff + o]);

    red[tid] = m * m;
    __syncthreads();
    for (int st = O >> 1; st > 0; st >>= 1) {
        if (o < st) red[tid] += red[tid + st];
        __syncthreads();
    }
    if (o == 0) sqout[base] = red[tid];
}

// ---------------- pooling (two-phase) ----------------
__global__ void pool1_kernel() {
    int chunk = blockIdx.x, b = blockIdx.y, o = threadIdx.x;
    const float* y = g_y5 + (size_t)b * PP * 512 + (size_t)chunk * 128 * 512;
    float mx = -INFINITY, sm = 0.f;
    for (int p = 0; p < 128; p++) {
        float v = y[(size_t)p * 512 + o];
        mx = fmaxf(mx, v);
        sm += v;
    }
    g_pmax[(b * 8 + chunk) * 512 + o] = mx;
    g_psum[(b * 8 + chunk) * 512 + o] = sm;
}

__global__ void pool2_kernel() {
    int b = blockIdx.x, o = threadIdx.x;
    float mx = -INFINITY, sm = 0.f;
    #pragma unroll
    for (int c = 0; c < 8; c++) {
        mx = fmaxf(mx, g_pmax[(b * 8 + c) * 512 + o]);
        sm += g_psum[(b * 8 + c) * 512 + o];
    }
    g_feat[b * 1024 + o] = mx;
    g_feat[b * 1024 + 512 + o] = sm * (1.0f / PP);
}

// ---------------- MLP head ----------------
__global__ void head_kernel(const float* __restrict__ L1, const float* __restrict__ s6, const float* __restrict__ b6,
                            const float* __restrict__ L2, const float* __restrict__ bl2,
                            const float* __restrict__ s7, const float* __restrict__ b7,
                            const float* __restrict__ L3, const float* __restrict__ bl3,
                            float* __restrict__ out) {
    __shared__ float sf[1024];
    __shared__ float z1[512];
    __shared__ float z2[256];
    int b = blockIdx.x, t = threadIdx.x;
    sf[t] = g_feat[b * 1024 + t];
    sf[t + 512] = g_feat[b * 1024 + 512 + t];
    __syncthreads();
    {
        float a = 0.f;
        const float* r = L1 + (size_t)t * 1024;
        for (int j = 0; j < 1024; j++) a += sf[j] * r[j];
        a = a * s6[t] + b6[t];
        z1[t] = (a > 0.f) ? a : 0.2f * a;
    }
    __syncthreads();
    if (t < 256) {
        float a = 0.f;
        const float* r = L2 + (size_t)t * 512;
        for (int j = 0; j < 512; j++) a += z1[j] * r[j];
        a = (a + bl2[t]) * s7[t] + b7[t];
        a = (a > 0.f) ? a : 0.2f * a;
        z2[t] = a * L3[t];
    }
    __syncthreads();
    if (t < 128) z2[t] += z2[t + 128];
    __syncthreads();
    if (t < 64) z2[t] += z2[t + 64];
    __syncthreads();
    if (t < 32) {
        float v = z2[t] + z2[t + 32];
        #pragma unroll
        for (int o = 16; o; o >>= 1) v += __shfl_down_sync(0xffffffffu, v, o);
        if (t == 0) {
            float z = v + bl3[0];
            out[b] = 1.0f / (1.0f + expf(-z));
        }
    }
}

// ---------------- host orchestration ----------------
#define GEMM_SMEM (2 * 4 * TILE_BYTES)

static void run_stage(const __nv_bfloat16* hh, const __nv_bfloat16* hl, int lda, int coff,
                      int C, int O,
                      const __nv_bfloat16* wh, const __nv_bfloat16* wl,
                      const float* s, const float* bias, int outcoff,
                      float* uw, float* pd, float* sq) {
    mmagemm<<<dim3(PP / 128, PP / 128, BB), 256, GEMM_SMEM>>>(
        hh, hl, lda, (long)PP * lda, coff,
        hh, hl, lda, (long)PP * lda, coff,
        pd, PP, (long)PP * PP,
        C, sq, PP, nullptr, nullptr, EPI_PD);
    topk_kernel<<<BB * PP / 8, 256>>>();
    mmagemm<<<dim3((2 * O) / 128, (BB * PP) / 128, 1), 256, GEMM_SMEM>>>(
        hh, hl, lda, 0, coff,
        wh, wl, C, 0, 0,
        uw, 2 * O, 0,
        C, nullptr, 0, nullptr, nullptr, EPI_PLAIN);
    int G = 256 / O;
    agg_kernel<<<dim3(PP / G, BB), 256>>>(uw, s, bias, O, outcoff, sq);
}

extern "C" void kernel_launch(void* const* d_in, const int* in_sizes, int n_in,
                              void* d_out, int out_size) {
    const int* clusters;
    const float* features;
    if (in_sizes[0] == BB * PP) {
        clusters = (const int*)d_in[0];
        features = (const float*)d_in[1];
    } else {
        features = (const float*)d_in[0];
        clusters = (const int*)d_in[1];
    }
    const float* W1  = (const float*)d_in[2];
    const float* s1  = (const float*)d_in[3];
    const float* b1  = (const float*)d_in[4];
    const float* W2  = (const float*)d_in[5];
    const float* s2  = (const float*)d_in[6];
    const float* b2  = (const float*)d_in[7];
    const float* W3  = (const float*)d_in[8];
    const float* s3  = (const float*)d_in[9];
    const float* b3  = (const float*)d_in[10];
    const float* W4  = (const float*)d_in[11];
    const float* s4  = (const float*)d_in[12];
    const float* b4  = (const float*)d_in[13];
    const float* W5  = (const float*)d_in[14];
    const float* s5  = (const float*)d_in[15];
    const float* b5  = (const float*)d_in[16];
    const float* L1  = (const float*)d_in[17];
    const float* s6  = (const float*)d_in[18];
    const float* b6  = (const float*)d_in[19];
    const float* L2  = (const float*)d_in[20];
    const float* bl2 = (const float*)d_in[21];
    const float* s7  = (const float*)d_in[22];
    const float* b7  = (const float*)d_in[23];
    const float* L3  = (const float*)d_in[24];
    const float* bl3 = (const float*)d_in[25];
    float* out = (float*)d_out;

    cudaFuncSetAttribute(mmagemm, cudaFuncAttributeMaxDynamicSharedMemorySize, GEMM_SMEM);

    float *h0, *uw, *pd, *sq, *y5;
    __nv_bfloat16 *h0h, *h0l, *xch, *xcl;
    __nv_bfloat16 *w1h, *w1l, *w2h, *w2l, *w3h, *w3l, *w4h, *w4l, *w5h, *w5l;
    cudaGetSymbolAddress((void**)&h0, g_h0);
    cudaGetSymbolAddress((void**)&uw, g_uw);
    cudaGetSymbolAddress((void**)&pd, g_pd);
    cudaGetSymbolAddress((void**)&sq, g_sq);
    cudaGetSymbolAddress((void**)&y5, g_y5);
    cudaGetSymbolAddress((void**)&h0h, g_h0h);
    cudaGetSymbolAddress((void**)&h0l, g_h0l);
    cudaGetSymbolAddress((void**)&xch, g_xch);
    cudaGetSymbolAddress((void**)&xcl, g_xcl);
    cudaGetSymbolAddress((void**)&w1h, g_w1h); cudaGetSymbolAddress((void**)&w1l, g_w1l);
    cudaGetSymbolAddress((void**)&w2h, g_w2h); cudaGetSymbolAddress((void**)&w2l, g_w2l);
    cudaGetSymbolAddress((void**)&w3h, g_w3h); cudaGetSymbolAddress((void**)&w3l, g_w3l);
    cudaGetSymbolAddress((void**)&w4h, g_w4h); cudaGetSymbolAddress((void**)&w4l, g_w4l);
    cudaGetSymbolAddress((void**)&w5h, g_w5h); cudaGetSymbolAddress((void**)&w5l, g_w5l);

    gather_kernel<<<(BB * PP * 32 + 255) / 256, 256>>>(features, clusters);
    sq_kernel<<<BB * PP / 8, 256>>>(h0, 128, 128);
    prep_kernel<<<(8192 + 4096 + 8192 + 32768 + 262144 + 255) / 256, 256>>>(W1, W2, W3, W4, W5);

    run_stage(h0h, h0l, 128, 0,   128, 64,  w1h, w1l, s1, b1, 0,   uw, pd, sq);
    run_stage(xch, xcl, 512, 0,   64,  64,  w2h, w2l, s2, b2, 64,  uw, pd, sq);
    run_stage(xch, xcl, 512, 64,  64,  128, w3h, w3l, s3, b3, 128, uw, pd, sq);
    run_stage(xch, xcl, 512, 128, 128, 256, w4h, w4l, s4, b4, 256, uw, pd, sq);

    // conv5: y5 = lrelu(s5 * (xc @ W5^T) + b5), K=512 in one kernel
    mmagemm<<<dim3(4, (BB * PP) / 128, 1), 256, GEMM_SMEM>>>(
        xch, xcl, 512, 0, 0,
        w5h, w5l, 512, 0, 0,
        y5, 512, 0,
        512, nullptr, 0, s5, b5, EPI_BN);

    pool1_kernel<<<dim3(8, BB), 512>>>();
    pool2_kernel<<<BB, 512>>>();
    head_kernel<<<BB, 512>>>(L1, s6, b6, L2, bl2, s7, b7, L3, bl3, out);
}

// round 7
// speedup vs baseline: 1.5151x; 1.0433x over previous
#include <cuda_runtime.h>
#include <cuda_bf16.h>
#include <math.h>
#include <stdint.h>

#define BB 16
#define PP 1024
#define KNN 20

// ---------------- scratch ----------------
__device__ float g_h0[BB * PP * 128];
__device__ __nv_bfloat16 g_h0h[BB * PP * 128];
__device__ __nv_bfloat16 g_h0l[BB * PP * 128];
__device__ __nv_bfloat16 g_xch[BB * PP * 512];
__device__ __nv_bfloat16 g_xcl[BB * PP * 512];
__device__ float g_uw[BB * PP * 512];
__device__ float g_pd[BB * PP * PP];
__device__ int   g_knn[BB * PP * KNN];
__device__ float g_y5[BB * PP * 512];
__device__ float g_feat[BB * 1024];
__device__ float g_sq[BB * PP];
__device__ float g_pmax[BB * 8 * 512];
__device__ float g_psum[BB * 8 * 512];
__device__ __nv_bfloat16 g_w1h[128 * 128], g_w1l[128 * 128];
__device__ __nv_bfloat16 g_w2h[128 * 64],  g_w2l[128 * 64];
__device__ __nv_bfloat16 g_w3h[256 * 64],  g_w3l[256 * 64];
__device__ __nv_bfloat16 g_w4h[512 * 128], g_w4l[512 * 128];
__device__ __nv_bfloat16 g_w5h[512 * 512], g_w5l[512 * 512];

__device__ __forceinline__ void bsplit(float x, __nv_bfloat16& hi, __nv_bfloat16& lo) {
    hi = __float2bfloat16(x);
    lo = __float2bfloat16(x - __bfloat162float(hi));
}

__device__ __forceinline__ uint32_t smem_u32(const void* p) {
    uint32_t a;
    asm("{ .reg .u64 t; cvta.to.shared.u64 t, %1; cvt.u32.u64 %0, t; }" : "=r"(a) : "l"(p));
    return a;
}

__device__ __forceinline__ void cp_async16(uint32_t dst, const void* src) {
    asm volatile("cp.async.ca.shared.global [%0], [%1], 16;"
                 :: "r"(dst), "l"(__cvta_generic_to_global(src)));
}
#define CP_COMMIT() asm volatile("cp.async.commit_group;")

__device__ __forceinline__ void mma16816(float* c, const uint32_t* a, const uint32_t* b) {
    asm volatile(
        "mma.sync.aligned.m16n8k16.row.col.f32.bf16.bf16.f32 "
        "{%0,%1,%2,%3}, {%4,%5,%6,%7}, {%8,%9}, {%0,%1,%2,%3};"
        : "+f"(c[0]), "+f"(c[1]), "+f"(c[2]), "+f"(c[3])
        : "r"(a[0]), "r"(a[1]), "r"(a[2]), "r"(a[3]), "r"(b[0]), "r"(b[1]));
}

// ---------------- gather ----------------
__global__ void gather_kernel(const float* __restrict__ feats, const int* __restrict__ clusters) {
    int t = blockIdx.x * blockDim.x + threadIdx.x;
    if (t >= BB * PP * 32) return;
    int c4 = t & 31, bp = t >> 5;
    int src = clusters[bp];
    float4 v = reinterpret_cast<const float4*>(feats)[(size_t)src * 32 + c4];
    reinterpret_cast<float4*>(g_h0)[(size_t)bp * 32 + c4] = v;
    size_t e = (size_t)bp * 128 + c4 * 4;
    bsplit(v.x, g_h0h[e + 0], g_h0l[e + 0]);
    bsplit(v.y, g_h0h[e + 1], g_h0l[e + 1]);
    bsplit(v.z, g_h0h[e + 2], g_h0l[e + 2]);
    bsplit(v.w, g_h0h[e + 3], g_h0l[e + 3]);
}

// ---------------- squared norms (stage 1) ----------------
__global__ void sq_kernel(const float* __restrict__ h, int lda, int C) {
    int warp = (blockIdx.x * blockDim.x + threadIdx.x) >> 5;
    int lane = threadIdx.x & 31;
    if (warp >= BB * PP) return;
    const float* row = h + (size_t)warp * lda;
    float s = 0.f;
    for (int c = lane; c < C; c += 32) { float v = row[c]; s += v * v; }
    #pragma unroll
    for (int o = 16; o; o >>= 1) s += __shfl_xor_sync(0xffffffffu, s, o);
    if (lane == 0) g_sq[warp] = s;
}

// ---------------- merged weight prep ----------------
__global__ void prep_kernel(const float* __restrict__ W1, const float* __restrict__ W2,
                            const float* __restrict__ W3, const float* __restrict__ W4,
                            const float* __restrict__ W5) {
    int t = blockIdx.x * blockDim.x + threadIdx.x;
    if (t < 8192) {
        int o = t / 128, c = t % 128;
        float wa = W1[(size_t)o * 256 + c], wb = W1[(size_t)o * 256 + 128 + c];
        bsplit(wa, g_w1h[o * 128 + c], g_w1l[o * 128 + c]);
        bsplit(wb - wa, g_w1h[(64 + o) * 128 + c], g_w1l[(64 + o) * 128 + c]);
        return;
    }
    t -= 8192;
    if (t < 4096) {
        int o = t / 64, c = t % 64;
        float wa = W2[(size_t)o * 128 + c], wb = W2[(size_t)o * 128 + 64 + c];
        bsplit(wa, g_w2h[o * 64 + c], g_w2l[o * 64 + c]);
        bsplit(wb - wa, g_w2h[(64 + o) * 64 + c], g_w2l[(64 + o) * 64 + c]);
        return;
    }
    t -= 4096;
    if (t < 8192) {
        int o = t / 64, c = t % 64;
        float wa = W3[(size_t)o * 128 + c], wb = W3[(size_t)o * 128 + 64 + c];
        bsplit(wa, g_w3h[o * 64 + c], g_w3l[o * 64 + c]);
        bsplit(wb - wa, g_w3h[(128 + o) * 64 + c], g_w3l[(128 + o) * 64 + c]);
        return;
    }
    t -= 8192;
    if (t < 32768) {
        int o = t / 128, c = t % 128;
        float wa = W4[(size_t)o * 256 + c], wb = W4[(size_t)o * 256 + 128 + c];
        bsplit(wa, g_w4h[o * 128 + c], g_w4l[o * 128 + c]);
        bsplit(wb - wa, g_w4h[(256 + o) * 128 + c], g_w4l[(256 + o) * 128 + c]);
        return;
    }
    t -= 32768;
    if (t < 262144) {
        bsplit(W5[t], g_w5h[t], g_w5l[t]);
    }
}

// ---------------- mma.sync split-bf16 GEMM ----------------
#define EPI_PLAIN 0
#define EPI_PD    1
#define EPI_BN    2

#define STRIDE_W 20
#define TILE_BYTES (128 * STRIDE_W * 4)

__global__ void __launch_bounds__(256)
mmagemm(const __nv_bfloat16* __restrict__ Ahi, const __nv_bfloat16* __restrict__ Alo,
        int lda, long sA, int acoff,
        const __nv_bfloat16* __restrict__ Bhi, const __nv_bfloat16* __restrict__ Blo,
        int ldb, long sB, int bcoff,
        float* __restrict__ Cout, int ldc, long sC,
        int K,
        const float* __restrict__ sq, long sSq,
        const float* __restrict__ bn_s, const float* __restrict__ bn_b, int epi) {
    extern __shared__ char dsm[];
    uint32_t smem_base = smem_u32(dsm);
    int tid = threadIdx.x;
    int lane = tid & 31, wid = tid >> 5;
    int warp_m = wid & 3, warp_n = wid >> 2;
    int g = lane >> 2, tid4 = lane & 3;
    int b = blockIdx.z;
    Ahi += (size_t)b * sA; Alo += (size_t)b * sA;
    Bhi += (size_t)b * sB; Blo += (size_t)b * sB;
    Cout += (size_t)b * sC;
    const float* sqb = sq + (size_t)b * sSq;

    size_t aRow = (size_t)blockIdx.y * 128;
    size_t bRow = (size_t)blockIdx.x * 128;
    int nKb = K >> 5;

    float acc[2][8][4];
    #pragma unroll
    for (int mf = 0; mf < 2; mf++)
        #pragma unroll
        for (int nf = 0; nf < 8; nf++)
            #pragma unroll
            for (int i = 0; i < 4; i++) acc[mf][nf][i] = 0.f;

    auto load_block = [&](int buf, int kb) {
        uint32_t sbuf = smem_base + buf * 4 * TILE_BYTES;
        #pragma unroll
        for (int it = 0; it < 8; it++) {
            int i = tid + it * 256;
            int tile = i >> 9;
            int rem = i & 511;
            int row = rem >> 2;
            int chunk = rem & 3;
            uint32_t dst = sbuf + tile * TILE_BYTES + row * (STRIDE_W * 4) + chunk * 16;
            const __nv_bfloat16* src;
            if (tile == 0)      src = Ahi + (aRow + row) * lda + acoff + kb * 32 + chunk * 8;
            else if (tile == 1) src = Alo + (aRow + row) * lda + acoff + kb * 32 + chunk * 8;
            else if (tile == 2) src = Bhi + (bRow + row) * ldb + bcoff + kb * 32 + chunk * 8;
            else                src = Blo + (bRow + row) * ldb + bcoff + kb * 32 + chunk * 8;
            cp_async16(dst, src);
        }
        CP_COMMIT();
    };

    load_block(0, 0);
    int buf = 0;
    for (int kb = 0; kb < nKb; kb++) {
        bool pref = (kb + 1 < nKb);
        if (pref) load_block(buf ^ 1, kb + 1);
        if (pref) asm volatile("cp.async.wait_group 1;");
        else      asm volatile("cp.async.wait_group 0;");
        __syncthreads();

        const uint32_t* sAh = (const uint32_t*)(dsm + buf * 4 * TILE_BYTES);
        const uint32_t* sAl = sAh + (TILE_BYTES / 4);
        const uint32_t* sBh = sAh + 2 * (TILE_BYTES / 4);
        const uint32_t* sBl = sAh + 3 * (TILE_BYTES / 4);

        #pragma unroll
        for (int s = 0; s < 2; s++) {
            int pk0 = s * 8;
            uint32_t ah[2][4], al[2][4];
            #pragma unroll
            for (int mf = 0; mf < 2; mf++) {
                int R = warp_m * 32 + mf * 16;
                int base0 = (R + g) * STRIDE_W + pk0 + tid4;
                int base1 = (R + g + 8) * STRIDE_W + pk0 + tid4;
                ah[mf][0] = sAh[base0]; ah[mf][1] = sAh[base1];
                ah[mf][2] = sAh[base0 + 4]; ah[mf][3] = sAh[base1 + 4];
                al[mf][0] = sAl[base0]; al[mf][1] = sAl[base1];
                al[mf][2] = sAl[base0 + 4]; al[mf][3] = sAl[base1 + 4];
            }
            #pragma unroll
            for (int nf = 0; nf < 8; nf++) {
                int NR = warp_n * 64 + nf * 8 + g;
                int nb = NR * STRIDE_W + pk0 + tid4;
                uint32_t bh[2], bl[2];
                bh[0] = sBh[nb]; bh[1] = sBh[nb + 4];
                bl[0] = sBl[nb]; bl[1] = sBl[nb + 4];
                #pragma unroll
                for (int mf = 0; mf < 2; mf++) {
                    mma16816(acc[mf][nf], ah[mf], bh);
                    mma16816(acc[mf][nf], al[mf], bh);
                    mma16816(acc[mf][nf], ah[mf], bl);
                }
            }
        }
        __syncthreads();
        buf ^= 1;
    }

    // epilogue (PD: per-row constant dropped — ordering-invariant for topk)
    #pragma unroll
    for (int mf = 0; mf < 2; mf++) {
        size_t r0 = aRow + warp_m * 32 + mf * 16 + g;
        size_t r1 = r0 + 8;
        #pragma unroll
        for (int nf = 0; nf < 8; nf++) {
            size_t c = (size_t)blockIdx.x * 128 + warp_n * 64 + nf * 8 + 2 * tid4;
            float v0 = acc[mf][nf][0], v1 = acc[mf][nf][1];
            float v2 = acc[mf][nf][2], v3 = acc[mf][nf][3];
            if (epi == EPI_PD) {
                float2 cs = *reinterpret_cast<const float2*>(&sqb[c]);
                v0 = 2.f * v0 - cs.x;
                v1 = 2.f * v1 - cs.y;
                v2 = 2.f * v2 - cs.x;
                v3 = 2.f * v3 - cs.y;
            } else if (epi == EPI_BN) {
                float2 cs = *reinterpret_cast<const float2*>(&bn_s[c]);
                float2 cb = *reinterpret_cast<const float2*>(&bn_b[c]);
                v0 = v0 * cs.x + cb.x; v0 = (v0 > 0.f) ? v0 : 0.2f * v0;
                v1 = v1 * cs.y + cb.y; v1 = (v1 > 0.f) ? v1 : 0.2f * v1;
                v2 = v2 * cs.x + cb.x; v2 = (v2 > 0.f) ? v2 : 0.2f * v2;
                v3 = v3 * cs.y + cb.y; v3 = (v3 > 0.f) ? v3 : 0.2f * v3;
            }
            *reinterpret_cast<float2*>(&Cout[r0 * ldc + c]) = make_float2(v0, v1);
            *reinterpret_cast<float2*>(&Cout[r1 * ldc + c]) = make_float2(v2, v3);
        }
    }
}

// ---------------- top-20 per row: fully register-resident ----------------
__global__ void __launch_bounds__(256) topk_kernel() {
    int warp = threadIdx.x >> 5, lane = threadIdx.x & 31;
    int row = blockIdx.x * 8 + warp;
    const float* __restrict__ prow = g_pd + (size_t)row * PP;

    float v[32];
    #pragma unroll
    for (int slot = 0; slot < 32; slot++) v[slot] = __ldg(&prow[slot * 32 + lane]);

    float m1 = -INFINITY, m2 = -INFINITY;
    int i1 = PP, i2 = PP;
    #pragma unroll
    for (int slot = 0; slot < 32; slot++) {
        float x = v[slot];
        int j = slot * 32 + lane;
        if (x > m1) { m2 = m1; i2 = i1; m1 = x; i1 = j; }
        else if (x > m2) { m2 = x; i2 = j; }
    }
    bool have2 = true;
    unsigned mask = 0;

    for (int k = 0; k < KNN; k++) {
        float best = m1; int bi = i1;
        #pragma unroll
        for (int o = 16; o; o >>= 1) {
            float ov = __shfl_xor_sync(0xffffffffu, best, o);
            int   oi = __shfl_xor_sync(0xffffffffu, bi, o);
            if (ov > best || (ov == best && oi < bi)) { best = ov; bi = oi; }
        }
        if (lane == 0) g_knn[row * KNN + k] = bi;
        if (i1 == bi) {
            mask |= 1u << (bi >> 5);
            if (have2) { m1 = m2; i1 = i2; have2 = false; }
            else {
                m1 = -INFINITY; m2 = -INFINITY; i1 = PP; i2 = PP;
                #pragma unroll
                for (int slot = 0; slot < 32; slot++) {
                    if (!(mask & (1u << slot))) {
                        float x = v[slot];
                        int j = slot * 32 + lane;
                        if (x > m1) { m2 = m1; i2 = i1; m1 = x; i1 = j; }
                        else if (x > m2) { m2 = x; i2 = j; }
                    }
                }
                have2 = true;
            }
        }
    }
}

// ---------------- aggregate + fused next-stage sq + bf16 split output ----------------
__global__ void __launch_bounds__(256) agg_kernel(
    const float* __restrict__ uw,
    const float* __restrict__ s, const float* __restrict__ bias,
    int O, int coloff, float* __restrict__ sqout) {
    __shared__ int sidx[128];
    __shared__ float red[256];
    int tid = threadIdx.x;
    int G = 256 / O;
    int pi = tid / O;
    int o = tid - pi * O;
    int b = blockIdx.y;
    int p = blockIdx.x * G + pi;
    size_t base = (size_t)b * PP + p;

    if (tid < G * KNN) {
        int gp = tid / KNN, kk = tid - gp * KNN;
        sidx[tid] = g_knn[((size_t)b * PP + blockIdx.x * G + gp) * KNN + kk];
    }
    __syncthreads();

    int twoO = 2 * O;
    const float* __restrict__ ub = uw + (size_t)b * PP * twoO;
    float wv = __ldg(&ub[(size_t)p * twoO + O + o]);
    float sv = s[o], bv = bias[o];
    const int* idx = sidx + pi * KNN;
    float m = -INFINITY;
    #pragma unroll
    for (int k = 0; k < KNN; k++) {
        int nb = idx[k];
        float y = __ldg(&ub[(size_t)nb * twoO + o]) + wv;
        y = y * sv + bv;
        y = (y > 0.f) ? y : 0.2f * y;
        m = fmaxf(m, y);
    }
    bsplit(m, g_xch[base * 512 + coloff + o], g_xcl[base * 512 + coloff + o]);

    red[tid] = m * m;
    __syncthreads();
    for (int st = O >> 1; st > 0; st >>= 1) {
        if (o < st) red[tid] += red[tid + st];
        __syncthreads();
    }
    if (o == 0) sqout[base] = red[tid];
}

// ---------------- pooling ----------------
__global__ void pool1_kernel() {
    int chunk = blockIdx.x, b = blockIdx.y, o = threadIdx.x;
    const float* y = g_y5 + (size_t)b * PP * 512 + (size_t)chunk * 128 * 512;
    float mx = -INFINITY, sm = 0.f;
    for (int p = 0; p < 128; p++) {
        float v = y[(size_t)p * 512 + o];
        mx = fmaxf(mx, v);
        sm += v;
    }
    g_pmax[(b * 8 + chunk) * 512 + o] = mx;
    g_psum[(b * 8 + chunk) * 512 + o] = sm;
}

__global__ void pool2_kernel() {
    int b = blockIdx.x, o = threadIdx.x;
    float mx = -INFINITY, sm = 0.f;
    #pragma unroll
    for (int c = 0; c < 8; c++) {
        mx = fmaxf(mx, g_pmax[(b * 8 + c) * 512 + o]);
        sm += g_psum[(b * 8 + c) * 512 + o];
    }
    g_feat[b * 1024 + o] = mx;
    g_feat[b * 1024 + 512 + o] = sm * (1.0f / PP);
}

// ---------------- MLP head ----------------
__global__ void head_kernel(const float* __restrict__ L1, const float* __restrict__ s6, const float* __restrict__ b6,
                            const float* __restrict__ L2, const float* __restrict__ bl2,
                            const float* __restrict__ s7, const float* __restrict__ b7,
                            const float* __restrict__ L3, const float* __restrict__ bl3,
                            float* __restrict__ out) {
    __shared__ float sf[1024];
    __shared__ float z1[512];
    __shared__ float z2[256];
    int b = blockIdx.x, t = threadIdx.x;
    sf[t] = g_feat[b * 1024 + t];
    sf[t + 512] = g_feat[b * 1024 + 512 + t];
    __syncthreads();
    {
        float a = 0.f;
        const float* r = L1 + (size_t)t * 1024;
        for (int j = 0; j < 1024; j++) a += sf[j] * r[j];
        a = a * s6[t] + b6[t];
        z1[t] = (a > 0.f) ? a : 0.2f * a;
    }
    __syncthreads();
    if (t < 256) {
        float a = 0.f;
        const float* r = L2 + (size_t)t * 512;
        for (int j = 0; j < 512; j++) a += z1[j] * r[j];
        a = (a + bl2[t]) * s7[t] + b7[t];
        a = (a > 0.f) ? a : 0.2f * a;
        z2[t] = a * L3[t];
    }
    __syncthreads();
    if (t < 128) z2[t] += z2[t + 128];
    __syncthreads();
    if (t < 64) z2[t] += z2[t + 64];
    __syncthreads();
    if (t < 32) {
        float v = z2[t] + z2[t + 32];
        #pragma unroll
        for (int o = 16; o; o >>= 1) v += __shfl_down_sync(0xffffffffu, v, o);
        if (t == 0) {
            float z = v + bl3[0];
            out[b] = 1.0f / (1.0f + expf(-z));
        }
    }
}

// ---------------- host orchestration ----------------
#define GEMM_SMEM (2 * 4 * TILE_BYTES)

extern "C" void kernel_launch(void* const* d_in, const int* in_sizes, int n_in,
                              void* d_out, int out_size) {
    const int* clusters;
    const float* features;
    if (in_sizes[0] == BB * PP) {
        clusters = (const int*)d_in[0];
        features = (const float*)d_in[1];
    } else {
        features = (const float*)d_in[0];
        clusters = (const int*)d_in[1];
    }
    const float* W1  = (const float*)d_in[2];
    const float* s1p = (const float*)d_in[3];
    const float* b1  = (const float*)d_in[4];
    const float* W2  = (const float*)d_in[5];
    const float* s2  = (const float*)d_in[6];
    const float* b2  = (const float*)d_in[7];
    const float* W3  = (const float*)d_in[8];
    const float* s3  = (const float*)d_in[9];
    const float* b3  = (const float*)d_in[10];
    const float* W4  = (const float*)d_in[11];
    const float* s4  = (const float*)d_in[12];
    const float* b4  = (const float*)d_in[13];
    const float* W5  = (const float*)d_in[14];
    const float* s5  = (const float*)d_in[15];
    const float* b5  = (const float*)d_in[16];
    const float* L1  = (const float*)d_in[17];
    const float* s6  = (const float*)d_in[18];
    const float* b6  = (const float*)d_in[19];
    const float* L2  = (const float*)d_in[20];
    const float* bl2 = (const float*)d_in[21];
    const float* s7  = (const float*)d_in[22];
    const float* b7  = (const float*)d_in[23];
    const float* L3  = (const float*)d_in[24];
    const float* bl3 = (const float*)d_in[25];
    float* out = (float*)d_out;

    static cudaStream_t s1s = nullptr;
    static cudaEvent_t evA, evW[4], evX[4];
    if (!s1s) {
        cudaFuncSetAttribute(mmagemm, cudaFuncAttributeMaxDynamicSharedMemorySize, GEMM_SMEM);
        cudaStreamCreateWithFlags(&s1s, cudaStreamNonBlocking);
        cudaEventCreateWithFlags(&evA, cudaEventDisableTiming);
        for (int i = 0; i < 4; i++) {
            cudaEventCreateWithFlags(&evW[i], cudaEventDisableTiming);
            cudaEventCreateWithFlags(&evX[i], cudaEventDisableTiming);
        }
    }

    float *h0, *uw, *pd, *sq, *y5;
    __nv_bfloat16 *h0h, *h0l, *xch, *xcl;
    __nv_bfloat16 *w1h, *w1l, *w2h, *w2l, *w3h, *w3l, *w4h, *w4l, *w5h, *w5l;
    cudaGetSymbolAddress((void**)&h0, g_h0);
    cudaGetSymbolAddress((void**)&uw, g_uw);
    cudaGetSymbolAddress((void**)&pd, g_pd);
    cudaGetSymbolAddress((void**)&sq, g_sq);
    cudaGetSymbolAddress((void**)&y5, g_y5);
    cudaGetSymbolAddress((void**)&h0h, g_h0h);
    cudaGetSymbolAddress((void**)&h0l, g_h0l);
    cudaGetSymbolAddress((void**)&xch, g_xch);
    cudaGetSymbolAddress((void**)&xcl, g_xcl);
    cudaGetSymbolAddress((void**)&w1h, g_w1h); cudaGetSymbolAddress((void**)&w1l, g_w1l);
    cudaGetSymbolAddress((void**)&w2h, g_w2h); cudaGetSymbolAddress((void**)&w2l, g_w2l);
    cudaGetSymbolAddress((void**)&w3h, g_w3h); cudaGetSymbolAddress((void**)&w3l, g_w3l);
    cudaGetSymbolAddress((void**)&w4h, g_w4h); cudaGetSymbolAddress((void**)&w4l, g_w4l);
    cudaGetSymbolAddress((void**)&w5h, g_w5h); cudaGetSymbolAddress((void**)&w5l, g_w5l);

    const __nv_bfloat16* hh[4] = { h0h, xch, xch, xch };
    const __nv_bfloat16* hl[4] = { h0l, xcl, xcl, xcl };
    int lda_s[4]   = { 128, 512, 512, 512 };
    int coff_s[4]  = { 0, 0, 64, 128 };
    int C_s[4]     = { 128, 64, 64, 128 };
    int O_s[4]     = { 64, 64, 128, 256 };
    const __nv_bfloat16* wh_s[4] = { w1h, w2h, w3h, w4h };
    const __nv_bfloat16* wl_s[4] = { w1l, w2l, w3l, w4l };
    const float* ss_s[4] = { s1p, s2, s3, s4 };
    const float* bb_s[4] = { b1, b2, b3, b4 };
    int ocoff_s[4] = { 0, 64, 128, 256 };

    // prep runs on side stream concurrently with gather/sq
    prep_kernel<<<(8192 + 4096 + 8192 + 32768 + 262144 + 255) / 256, 256, 0, s1s>>>(W1, W2, W3, W4, W5);
    gather_kernel<<<(BB * PP * 32 + 255) / 256, 256>>>(features, clusters);
    sq_kernel<<<BB * PP / 8, 256>>>(h0, 128, 128);
    cudaEventRecord(evA, 0);
    cudaStreamWaitEvent(s1s, evA, 0);

    for (int st = 0; st < 4; st++) {
        long strideA = (long)PP * lda_s[st];   // per-batch stride (FIX: valid for ALL stages)

        // uw on side stream
        mmagemm<<<dim3((2 * O_s[st]) / 128, (BB * PP) / 128, 1), 256, GEMM_SMEM, s1s>>>(
            hh[st], hl[st], lda_s[st], 0, coff_s[st],
            wh_s[st], wl_s[st], C_s[st], 0, 0,
            uw, 2 * O_s[st], 0,
            C_s[st], nullptr, 0, nullptr, nullptr, EPI_PLAIN);
        cudaEventRecord(evW[st], s1s);

        // pd + topk on main stream (batched over BB with proper stride)
        mmagemm<<<dim3(PP / 128, PP / 128, BB), 256, GEMM_SMEM>>>(
            hh[st], hl[st], lda_s[st], strideA, coff_s[st],
            hh[st], hl[st], lda_s[st], strideA, coff_s[st],
            pd, PP, (long)PP * PP,
            C_s[st], sq, PP, nullptr, nullptr, EPI_PD);
        topk_kernel<<<BB * PP / 8, 256>>>();

        cudaStreamWaitEvent(0, evW[st], 0);
        int G = 256 / O_s[st];
        agg_kernel<<<dim3(PP / G, BB), 256>>>(uw, ss_s[st], bb_s[st], O_s[st], ocoff_s[st], sq);
        if (st < 3) {
            cudaEventRecord(evX[st], 0);
            cudaStreamWaitEvent(s1s, evX[st], 0);
        }
    }

    // conv5 (needs full xc)
    mmagemm<<<dim3(4, (BB * PP) / 128, 1), 256, GEMM_SMEM>>>(
        xch, xcl, 512, 0, 0,
        w5h, w5l, 512, 0, 0,
        y5, 512, 0,
        512, nullptr, 0, s5, b5, EPI_BN);

    pool1_kernel<<<dim3(8, BB), 512>>>();
    pool2_kernel<<<BB, 512>>>();
    head_kernel<<<BB, 512>>>(L1, s6, b6, L2, bl2, s7, b7, L3, bl3, out);
}

// round 8
// speedup vs baseline: 1.6182x; 1.0681x over previous
#include <cuda_runtime.h>
#include <cuda_bf16.h>
#include <math.h>
#include <stdint.h>

#define BB 16
#define PP 1024
#define KNN 20

// ---------------- scratch ----------------
__device__ float g_h0[BB * PP * 128];
__device__ __nv_bfloat16 g_h0h[BB * PP * 128];
__device__ __nv_bfloat16 g_h0l[BB * PP * 128];
__device__ __nv_bfloat16 g_xch[BB * PP * 512];
__device__ __nv_bfloat16 g_xcl[BB * PP * 512];
__device__ float g_uw[BB * PP * 512];
__device__ float g_pd[BB * PP * PP];
__device__ int   g_knn[BB * PP * KNN];
__device__ float g_sq[BB * PP];
__device__ float g_pmax[BB * 8 * 512];
__device__ float g_psum[BB * 8 * 512];
__device__ __nv_bfloat16 g_w1h[128 * 128], g_w1l[128 * 128];
__device__ __nv_bfloat16 g_w2h[128 * 64],  g_w2l[128 * 64];
__device__ __nv_bfloat16 g_w3h[256 * 64],  g_w3l[256 * 64];
__device__ __nv_bfloat16 g_w4h[512 * 128], g_w4l[512 * 128];
__device__ __nv_bfloat16 g_w5h[512 * 512], g_w5l[512 * 512];

__device__ __forceinline__ void bsplit(float x, __nv_bfloat16& hi, __nv_bfloat16& lo) {
    hi = __float2bfloat16(x);
    lo = __float2bfloat16(x - __bfloat162float(hi));
}

__device__ __forceinline__ uint32_t smem_u32(const void* p) {
    uint32_t a;
    asm("{ .reg .u64 t; cvta.to.shared.u64 t, %1; cvt.u32.u64 %0, t; }" : "=r"(a) : "l"(p));
    return a;
}

__device__ __forceinline__ void cp_async16(uint32_t dst, const void* src) {
    asm volatile("cp.async.ca.shared.global [%0], [%1], 16;"
                 :: "r"(dst), "l"(__cvta_generic_to_global(src)));
}
#define CP_COMMIT() asm volatile("cp.async.commit_group;")

__device__ __forceinline__ void mma16816(float* c, const uint32_t* a, const uint32_t* b) {
    asm volatile(
        "mma.sync.aligned.m16n8k16.row.col.f32.bf16.bf16.f32 "
        "{%0,%1,%2,%3}, {%4,%5,%6,%7}, {%8,%9}, {%0,%1,%2,%3};"
        : "+f"(c[0]), "+f"(c[1]), "+f"(c[2]), "+f"(c[3])
        : "r"(a[0]), "r"(a[1]), "r"(a[2]), "r"(a[3]), "r"(b[0]), "r"(b[1]));
}

// ---------------- gather ----------------
__global__ void gather_kernel(const float* __restrict__ feats, const int* __restrict__ clusters) {
    int t = blockIdx.x * blockDim.x + threadIdx.x;
    if (t >= BB * PP * 32) return;
    int c4 = t & 31, bp = t >> 5;
    int src = clusters[bp];
    float4 v = reinterpret_cast<const float4*>(feats)[(size_t)src * 32 + c4];
    reinterpret_cast<float4*>(g_h0)[(size_t)bp * 32 + c4] = v;
    size_t e = (size_t)bp * 128 + c4 * 4;
    bsplit(v.x, g_h0h[e + 0], g_h0l[e + 0]);
    bsplit(v.y, g_h0h[e + 1], g_h0l[e + 1]);
    bsplit(v.z, g_h0h[e + 2], g_h0l[e + 2]);
    bsplit(v.w, g_h0h[e + 3], g_h0l[e + 3]);
}

// ---------------- squared norms (stage 1) ----------------
__global__ void sq_kernel(const float* __restrict__ h, int lda, int C) {
    int warp = (blockIdx.x * blockDim.x + threadIdx.x) >> 5;
    int lane = threadIdx.x & 31;
    if (warp >= BB * PP) return;
    const float* row = h + (size_t)warp * lda;
    float s = 0.f;
    for (int c = lane; c < C; c += 32) { float v = row[c]; s += v * v; }
    #pragma unroll
    for (int o = 16; o; o >>= 1) s += __shfl_xor_sync(0xffffffffu, s, o);
    if (lane == 0) g_sq[warp] = s;
}

// ---------------- merged weight prep ----------------
__global__ void prep_kernel(const float* __restrict__ W1, const float* __restrict__ W2,
                            const float* __restrict__ W3, const float* __restrict__ W4,
                            const float* __restrict__ W5) {
    int t = blockIdx.x * blockDim.x + threadIdx.x;
    if (t < 8192) {
        int o = t / 128, c = t % 128;
        float wa = W1[(size_t)o * 256 + c], wb = W1[(size_t)o * 256 + 128 + c];
        bsplit(wa, g_w1h[o * 128 + c], g_w1l[o * 128 + c]);
        bsplit(wb - wa, g_w1h[(64 + o) * 128 + c], g_w1l[(64 + o) * 128 + c]);
        return;
    }
    t -= 8192;
    if (t < 4096) {
        int o = t / 64, c = t % 64;
        float wa = W2[(size_t)o * 128 + c], wb = W2[(size_t)o * 128 + 64 + c];
        bsplit(wa, g_w2h[o * 64 + c], g_w2l[o * 64 + c]);
        bsplit(wb - wa, g_w2h[(64 + o) * 64 + c], g_w2l[(64 + o) * 64 + c]);
        return;
    }
    t -= 4096;
    if (t < 8192) {
        int o = t / 64, c = t % 64;
        float wa = W3[(size_t)o * 128 + c], wb = W3[(size_t)o * 128 + 64 + c];
        bsplit(wa, g_w3h[o * 64 + c], g_w3l[o * 64 + c]);
        bsplit(wb - wa, g_w3h[(128 + o) * 64 + c], g_w3l[(128 + o) * 64 + c]);
        return;
    }
    t -= 8192;
    if (t < 32768) {
        int o = t / 128, c = t % 128;
        float wa = W4[(size_t)o * 256 + c], wb = W4[(size_t)o * 256 + 128 + c];
        bsplit(wa, g_w4h[o * 128 + c], g_w4l[o * 128 + c]);
        bsplit(wb - wa, g_w4h[(256 + o) * 128 + c], g_w4l[(256 + o) * 128 + c]);
        return;
    }
    t -= 32768;
    if (t < 262144) {
        bsplit(W5[t], g_w5h[t], g_w5l[t]);
    }
}

// ---------------- shared GEMM mainloop macro pieces ----------------
#define EPI_PLAIN 0
#define EPI_POOL  2

#define STRIDE_W 20
#define TILE_BYTES (128 * STRIDE_W * 4)
#define GEMM_SMEM (2 * 4 * TILE_BYTES)

// ---------------- generic split-bf16 GEMM: C = A*B^T, templated epilogue ----------------
template<int EPI>
__global__ void __launch_bounds__(256)
mmagemm(const __nv_bfloat16* __restrict__ Ahi, const __nv_bfloat16* __restrict__ Alo,
        int lda, long sA, int acoff,
        const __nv_bfloat16* __restrict__ Bhi, const __nv_bfloat16* __restrict__ Blo,
        int ldb, long sB, int bcoff,
        float* __restrict__ Cout, int ldc, long sC,
        int K,
        const float* __restrict__ bn_s, const float* __restrict__ bn_b,
        float* __restrict__ pmax, float* __restrict__ psum) {
    extern __shared__ char dsm[];
    uint32_t smem_base = smem_u32(dsm);
    int tid = threadIdx.x;
    int lane = tid & 31, wid = tid >> 5;
    int warp_m = wid & 3, warp_n = wid >> 2;
    int g = lane >> 2, tid4 = lane & 3;
    int b = blockIdx.z;
    Ahi += (size_t)b * sA; Alo += (size_t)b * sA;
    Bhi += (size_t)b * sB; Blo += (size_t)b * sB;
    Cout += (size_t)b * sC;

    size_t aRow = (size_t)blockIdx.y * 128;
    size_t bRow = (size_t)blockIdx.x * 128;
    int nKb = K >> 5;

    float acc[2][8][4];
    #pragma unroll
    for (int mf = 0; mf < 2; mf++)
        #pragma unroll
        for (int nf = 0; nf < 8; nf++)
            #pragma unroll
            for (int i = 0; i < 4; i++) acc[mf][nf][i] = 0.f;

    auto load_block = [&](int buf, int kb) {
        uint32_t sbuf = smem_base + buf * 4 * TILE_BYTES;
        #pragma unroll
        for (int it = 0; it < 8; it++) {
            int i = tid + it * 256;
            int tile = i >> 9;
            int rem = i & 511;
            int row = rem >> 2;
            int chunk = rem & 3;
            uint32_t dst = sbuf + tile * TILE_BYTES + row * (STRIDE_W * 4) + chunk * 16;
            const __nv_bfloat16* src;
            if (tile == 0)      src = Ahi + (aRow + row) * lda + acoff + kb * 32 + chunk * 8;
            else if (tile == 1) src = Alo + (aRow + row) * lda + acoff + kb * 32 + chunk * 8;
            else if (tile == 2) src = Bhi + (bRow + row) * ldb + bcoff + kb * 32 + chunk * 8;
            else                src = Blo + (bRow + row) * ldb + bcoff + kb * 32 + chunk * 8;
            cp_async16(dst, src);
        }
        CP_COMMIT();
    };

    load_block(0, 0);
    int buf = 0;
    for (int kb = 0; kb < nKb; kb++) {
        bool pref = (kb + 1 < nKb);
        if (pref) load_block(buf ^ 1, kb + 1);
        if (pref) asm volatile("cp.async.wait_group 1;");
        else      asm volatile("cp.async.wait_group 0;");
        __syncthreads();

        const uint32_t* sAh = (const uint32_t*)(dsm + buf * 4 * TILE_BYTES);
        const uint32_t* sAl = sAh + (TILE_BYTES / 4);
        const uint32_t* sBh = sAh + 2 * (TILE_BYTES / 4);
        const uint32_t* sBl = sAh + 3 * (TILE_BYTES / 4);

        #pragma unroll
        for (int s = 0; s < 2; s++) {
            int pk0 = s * 8;
            uint32_t ah[2][4], al[2][4];
            #pragma unroll
            for (int mf = 0; mf < 2; mf++) {
                int R = warp_m * 32 + mf * 16;
                int base0 = (R + g) * STRIDE_W + pk0 + tid4;
                int base1 = (R + g + 8) * STRIDE_W + pk0 + tid4;
                ah[mf][0] = sAh[base0]; ah[mf][1] = sAh[base1];
                ah[mf][2] = sAh[base0 + 4]; ah[mf][3] = sAh[base1 + 4];
                al[mf][0] = sAl[base0]; al[mf][1] = sAl[base1];
                al[mf][2] = sAl[base0 + 4]; al[mf][3] = sAl[base1 + 4];
            }
            #pragma unroll
            for (int nf = 0; nf < 8; nf++) {
                int NR = warp_n * 64 + nf * 8 + g;
                int nb = NR * STRIDE_W + pk0 + tid4;
                uint32_t bh[2], bl[2];
                bh[0] = sBh[nb]; bh[1] = sBh[nb + 4];
                bl[0] = sBl[nb]; bl[1] = sBl[nb + 4];
                #pragma unroll
                for (int mf = 0; mf < 2; mf++) {
                    mma16816(acc[mf][nf], ah[mf], bh);
                    mma16816(acc[mf][nf], al[mf], bh);
                    mma16816(acc[mf][nf], ah[mf], bl);
                }
            }
        }
        __syncthreads();
        buf ^= 1;
    }

    if (EPI == EPI_POOL) {
        // conv5 + BN + lrelu + block-level partial max/sum pooling (no C write)
        float tmax[16], tsum[16];
        #pragma unroll
        for (int j = 0; j < 16; j++) { tmax[j] = -INFINITY; tsum[j] = 0.f; }
        #pragma unroll
        for (int nf = 0; nf < 8; nf++) {
            int c = warp_n * 64 + nf * 8 + 2 * tid4;
            float2 cs = *reinterpret_cast<const float2*>(&bn_s[blockIdx.x * 128 + c]);
            float2 cb = *reinterpret_cast<const float2*>(&bn_b[blockIdx.x * 128 + c]);
            #pragma unroll
            for (int mf = 0; mf < 2; mf++) {
                float v0 = acc[mf][nf][0] * cs.x + cb.x; v0 = (v0 > 0.f) ? v0 : 0.2f * v0;
                float v1 = acc[mf][nf][1] * cs.y + cb.y; v1 = (v1 > 0.f) ? v1 : 0.2f * v1;
                float v2 = acc[mf][nf][2] * cs.x + cb.x; v2 = (v2 > 0.f) ? v2 : 0.2f * v2;
                float v3 = acc[mf][nf][3] * cs.y + cb.y; v3 = (v3 > 0.f) ? v3 : 0.2f * v3;
                tmax[nf * 2 + 0] = fmaxf(tmax[nf * 2 + 0], fmaxf(v0, v2));
                tmax[nf * 2 + 1] = fmaxf(tmax[nf * 2 + 1], fmaxf(v1, v3));
                tsum[nf * 2 + 0] += v0 + v2;
                tsum[nf * 2 + 1] += v1 + v3;
            }
        }
        #pragma unroll
        for (int off = 4; off <= 16; off <<= 1) {
            #pragma unroll
            for (int j = 0; j < 16; j++) {
                tmax[j] = fmaxf(tmax[j], __shfl_xor_sync(0xffffffffu, tmax[j], off));
                tsum[j] += __shfl_xor_sync(0xffffffffu, tsum[j], off);
            }
        }
        float* st = (float*)dsm;
        if (g == 0) {
            int base = ((warp_m * 2 + warp_n) * 4 + tid4) * 32;
            #pragma unroll
            for (int j = 0; j < 16; j++) { st[base + j] = tmax[j]; st[base + 16 + j] = tsum[j]; }
        }
        __syncthreads();
        if (warp_m == 0 && g == 0) {
            #pragma unroll
            for (int j = 0; j < 16; j++) {
                float m = -INFINITY, s = 0.f;
                #pragma unroll
                for (int wm = 0; wm < 4; wm++) {
                    int base = ((wm * 2 + warp_n) * 4 + tid4) * 32;
                    m = fmaxf(m, st[base + j]);
                    s += st[base + 16 + j];
                }
                int c = warp_n * 64 + (j >> 1) * 8 + 2 * tid4 + (j & 1);
                pmax[(size_t)blockIdx.y * 512 + blockIdx.x * 128 + c] = m;
                psum[(size_t)blockIdx.y * 512 + blockIdx.x * 128 + c] = s;
            }
        }
    } else {
        // plain C write
        #pragma unroll
        for (int mf = 0; mf < 2; mf++) {
            size_t r0 = aRow + warp_m * 32 + mf * 16 + g;
            size_t r1 = r0 + 8;
            #pragma unroll
            for (int nf = 0; nf < 8; nf++) {
                size_t c = (size_t)blockIdx.x * 128 + warp_n * 64 + nf * 8 + 2 * tid4;
                *reinterpret_cast<float2*>(&Cout[r0 * ldc + c]) = make_float2(acc[mf][nf][0], acc[mf][nf][1]);
                *reinterpret_cast<float2*>(&Cout[r1 * ldc + c]) = make_float2(acc[mf][nf][2], acc[mf][nf][3]);
            }
        }
    }
}

// ---------------- symmetric pd GEMM: only lower-triangle tiles, mirror via smem transpose ----------------
__global__ void __launch_bounds__(256)
pdsym(const __nv_bfloat16* __restrict__ Ahi, const __nv_bfloat16* __restrict__ Alo,
      int lda, long sA, int acoff, int K) {
    extern __shared__ char dsm[];
    uint32_t smem_base = smem_u32(dsm);
    int tid = threadIdx.x;
    int lane = tid & 31, wid = tid >> 5;
    int warp_m = wid & 3, warp_n = wid >> 2;
    int g = lane >> 2, tid4 = lane & 3;
    int b = blockIdx.z;
    const __nv_bfloat16* Hh = Ahi + (size_t)b * sA;
    const __nv_bfloat16* Hl = Alo + (size_t)b * sA;
    float* pd = g_pd + (size_t)b * PP * PP;
    const float* sqb = g_sq + (size_t)b * PP;

    // map blockIdx.x (0..35) -> (bx, by) with bx <= by
    int t36 = blockIdx.x, by = 0;
    while (t36 > by) { t36 -= by + 1; by++; }
    int bx = t36;

    size_t aRow = (size_t)by * 128;
    size_t bRow = (size_t)bx * 128;
    int nKb = K >> 5;

    float acc[2][8][4];
    #pragma unroll
    for (int mf = 0; mf < 2; mf++)
        #pragma unroll
        for (int nf = 0; nf < 8; nf++)
            #pragma unroll
            for (int i = 0; i < 4; i++) acc[mf][nf][i] = 0.f;

    auto load_block = [&](int buf, int kb) {
        uint32_t sbuf = smem_base + buf * 4 * TILE_BYTES;
        #pragma unroll
        for (int it = 0; it < 8; it++) {
            int i = tid + it * 256;
            int tile = i >> 9;
            int rem = i & 511;
            int row = rem >> 2;
            int chunk = rem & 3;
            uint32_t dst = sbuf + tile * TILE_BYTES + row * (STRIDE_W * 4) + chunk * 16;
            const __nv_bfloat16* src;
            if (tile == 0)      src = Hh + (aRow + row) * lda + acoff + kb * 32 + chunk * 8;
            else if (tile == 1) src = Hl + (aRow + row) * lda + acoff + kb * 32 + chunk * 8;
            else if (tile == 2) src = Hh + (bRow + row) * lda + acoff + kb * 32 + chunk * 8;
            else                src = Hl + (bRow + row) * lda + acoff + kb * 32 + chunk * 8;
            cp_async16(dst, src);
        }
        CP_COMMIT();
    };

    load_block(0, 0);
    int buf = 0;
    for (int kb = 0; kb < nKb; kb++) {
        bool pref = (kb + 1 < nKb);
        if (pref) load_block(buf ^ 1, kb + 1);
        if (pref) asm volatile("cp.async.wait_group 1;");
        else      asm volatile("cp.async.wait_group 0;");
        __syncthreads();

        const uint32_t* sAh = (const uint32_t*)(dsm + buf * 4 * TILE_BYTES);
        const uint32_t* sAl = sAh + (TILE_BYTES / 4);
        const uint32_t* sBh = sAh + 2 * (TILE_BYTES / 4);
        const uint32_t* sBl = sAh + 3 * (TILE_BYTES / 4);

        #pragma unroll
        for (int s = 0; s < 2; s++) {
            int pk0 = s * 8;
            uint32_t ah[2][4], al[2][4];
            #pragma unroll
            for (int mf = 0; mf < 2; mf++) {
                int R = warp_m * 32 + mf * 16;
                int base0 = (R + g) * STRIDE_W + pk0 + tid4;
                int base1 = (R + g + 8) * STRIDE_W + pk0 + tid4;
                ah[mf][0] = sAh[base0]; ah[mf][1] = sAh[base1];
                ah[mf][2] = sAh[base0 + 4]; ah[mf][3] = sAh[base1 + 4];
                al[mf][0] = sAl[base0]; al[mf][1] = sAl[base1];
                al[mf][2] = sAl[base0 + 4]; al[mf][3] = sAl[base1 + 4];
            }
            #pragma unroll
            for (int nf = 0; nf < 8; nf++) {
                int NR = warp_n * 64 + nf * 8 + g;
                int nb = NR * STRIDE_W + pk0 + tid4;
                uint32_t bh[2], bl[2];
                bh[0] = sBh[nb]; bh[1] = sBh[nb + 4];
                bl[0] = sBl[nb]; bl[1] = sBl[nb + 4];
                #pragma unroll
                for (int mf = 0; mf < 2; mf++) {
                    mma16816(acc[mf][nf], ah[mf], bh);
                    mma16816(acc[mf][nf], al[mf], bh);
                    mma16816(acc[mf][nf], ah[mf], bl);
                }
            }
        }
        __syncthreads();
        buf ^= 1;
    }

    // normal write: rows in by-tile, cols in bx-tile; pd[r,c] = 2g - sq_c
    #pragma unroll
    for (int mf = 0; mf < 2; mf++) {
        size_t r0 = aRow + warp_m * 32 + mf * 16 + g;
        size_t r1 = r0 + 8;
        #pragma unroll
        for (int nf = 0; nf < 8; nf++) {
            size_t c = bRow + warp_n * 64 + nf * 8 + 2 * tid4;
            float2 cs = *reinterpret_cast<const float2*>(&sqb[c]);
            *reinterpret_cast<float2*>(&pd[r0 * PP + c]) =
                make_float2(2.f * acc[mf][nf][0] - cs.x, 2.f * acc[mf][nf][1] - cs.y);
            *reinterpret_cast<float2*>(&pd[r1 * PP + c]) =
                make_float2(2.f * acc[mf][nf][2] - cs.x, 2.f * acc[mf][nf][3] - cs.y);
        }
    }

    if (bx != by) {
        // stage 2g into padded smem, then write mirrored tile: pd[c', r'] = 2g - sq_r'
        float* st = (float*)dsm;
        #pragma unroll
        for (int mf = 0; mf < 2; mf++) {
            int rl0 = warp_m * 32 + mf * 16 + g;
            int rl1 = rl0 + 8;
            #pragma unroll
            for (int nf = 0; nf < 8; nf++) {
                int cl = warp_n * 64 + nf * 8 + 2 * tid4;
                st[rl0 * 129 + cl]     = 2.f * acc[mf][nf][0];
                st[rl0 * 129 + cl + 1] = 2.f * acc[mf][nf][1];
                st[rl1 * 129 + cl]     = 2.f * acc[mf][nf][2];
                st[rl1 * 129 + cl + 1] = 2.f * acc[mf][nf][3];
            }
        }
        __syncthreads();
        for (int i = tid; i < 128 * 32; i += 256) {
            int cl = i >> 5;              // col of g-tile = row of mirrored tile
            int r  = (i & 31) * 4;        // row of g-tile (4 at a time)
            float4 sv;
            sv.x = st[(r + 0) * 129 + cl];
            sv.y = st[(r + 1) * 129 + cl];
            sv.z = st[(r + 2) * 129 + cl];
            sv.w = st[(r + 3) * 129 + cl];
            float4 sq4 = *reinterpret_cast<const float4*>(&sqb[aRow + r]);
            float4 o = make_float4(sv.x - sq4.x, sv.y - sq4.y, sv.z - sq4.z, sv.w - sq4.w);
            *reinterpret_cast<float4*>(&pd[(bRow + cl) * PP + aRow + r]) = o;
        }
    }
}

// ---------------- top-20 per row: fully register-resident ----------------
__global__ void __launch_bounds__(256) topk_kernel() {
    int warp = threadIdx.x >> 5, lane = threadIdx.x & 31;
    int row = blockIdx.x * 8 + warp;
    const float* __restrict__ prow = g_pd + (size_t)row * PP;

    float v[32];
    #pragma unroll
    for (int slot = 0; slot < 32; slot++) v[slot] = __ldg(&prow[slot * 32 + lane]);

    float m1 = -INFINITY, m2 = -INFINITY;
    int i1 = PP, i2 = PP;
    #pragma unroll
    for (int slot = 0; slot < 32; slot++) {
        float x = v[slot];
        int j = slot * 32 + lane;
        if (x > m1) { m2 = m1; i2 = i1; m1 = x; i1 = j; }
        else if (x > m2) { m2 = x; i2 = j; }
    }
    bool have2 = true;
    unsigned mask = 0;

    for (int k = 0; k < KNN; k++) {
        float best = m1; int bi = i1;
        #pragma unroll
        for (int o = 16; o; o >>= 1) {
            float ov = __shfl_xor_sync(0xffffffffu, best, o);
            int   oi = __shfl_xor_sync(0xffffffffu, bi, o);
            if (ov > best || (ov == best && oi < bi)) { best = ov; bi = oi; }
        }
        if (lane == 0) g_knn[row * KNN + k] = bi;
        if (i1 == bi) {
            mask |= 1u << (bi >> 5);
            if (have2) { m1 = m2; i1 = i2; have2 = false; }
            else {
                m1 = -INFINITY; m2 = -INFINITY; i1 = PP; i2 = PP;
                #pragma unroll
                for (int slot = 0; slot < 32; slot++) {
                    if (!(mask & (1u << slot))) {
                        float x = v[slot];
                        int j = slot * 32 + lane;
                        if (x > m1) { m2 = m1; i2 = i1; m1 = x; i1 = j; }
                        else if (x > m2) { m2 = x; i2 = j; }
                    }
                }
                have2 = true;
            }
        }
    }
}

// ---------------- aggregate + fused next-stage sq + bf16 split output ----------------
__global__ void __launch_bounds__(256) agg_kernel(
    const float* __restrict__ uw,
    const float* __restrict__ s, const float* __restrict__ bias,
    int O, int coloff, float* __restrict__ sqout) {
    __shared__ int sidx[128];
    __shared__ float red[256];
    int tid = threadIdx.x;
    int G = 256 / O;
    int pi = tid / O;
    int o = tid - pi * O;
    int b = blockIdx.y;
    int p = blockIdx.x * G + pi;
    size_t base = (size_t)b * PP + p;

    if (tid < G * KNN) {
        int gp = tid / KNN, kk = tid - gp * KNN;
        sidx[tid] = g_knn[((size_t)b * PP + blockIdx.x * G + gp) * KNN + kk];
    }
    __syncthreads();

    int twoO = 2 * O;
    const float* __restrict__ ub = uw + (size_t)b * PP * twoO;
    float wv = __ldg(&ub[(size_t)p * twoO + O + o]);
    float sv = s[o], bv = bias[o];
    const int* idx = sidx + pi * KNN;
    float m = -INFINITY;
    #pragma unroll
    for (int k = 0; k < KNN; k++) {
        int nb = idx[k];
        float y = __ldg(&ub[(size_t)nb * twoO + o]) + wv;
        y = y * sv + bv;
        y = (y > 0.f) ? y : 0.2f * y;
        m = fmaxf(m, y);
    }
    bsplit(m, g_xch[base * 512 + coloff + o], g_xcl[base * 512 + coloff + o]);

    red[tid] = m * m;
    __syncthreads();
    for (int st = O >> 1; st > 0; st >>= 1) {
        if (o < st) red[tid] += red[tid + st];
        __syncthreads();
    }
    if (o == 0) sqout[base] = red[tid];
}

// ---------------- MLP head (with inline pool combine) ----------------
__global__ void head_kernel(const float* __restrict__ L1, const float* __restrict__ s6, const float* __restrict__ b6,
                            const float* __restrict__ L2, const float* __restrict__ bl2,
                            const float* __restrict__ s7, const float* __restrict__ b7,
                            const float* __restrict__ L3, const float* __restrict__ bl3,
                            float* __restrict__ out) {
    __shared__ float sf[1024];
    __shared__ float z1[512];
    __shared__ float z2[256];
    int b = blockIdx.x, t = threadIdx.x;   // 512 threads
    {
        float mx = -INFINITY, sm = 0.f;
        #pragma unroll
        for (int c = 0; c < 8; c++) {
            mx = fmaxf(mx, g_pmax[(b * 8 + c) * 512 + t]);
            sm += g_psum[(b * 8 + c) * 512 + t];
        }
        sf[t] = mx;
        sf[t + 512] = sm * (1.0f / PP);
    }
    __syncthreads();
    {
        float a = 0.f;
        const float* r = L1 + (size_t)t * 1024;
        for (int j = 0; j < 1024; j++) a += sf[j] * r[j];
        a = a * s6[t] + b6[t];
        z1[t] = (a > 0.f) ? a : 0.2f * a;
    }
    __syncthreads();
    if (t < 256) {
        float a = 0.f;
        const float* r = L2 + (size_t)t * 512;
        for (int j = 0; j < 512; j++) a += z1[j] * r[j];
        a = (a + bl2[t]) * s7[t] + b7[t];
        a = (a > 0.f) ? a : 0.2f * a;
        z2[t] = a * L3[t];
    }
    __syncthreads();
    if (t < 128) z2[t] += z2[t + 128];
    __syncthreads();
    if (t < 64) z2[t] += z2[t + 64];
    __syncthreads();
    if (t < 32) {
        float v = z2[t] + z2[t + 32];
        #pragma unroll
        for (int o = 16; o; o >>= 1) v += __shfl_down_sync(0xffffffffu, v, o);
        if (t == 0) {
            float z = v + bl3[0];
            out[b] = 1.0f / (1.0f + expf(-z));
        }
    }
}

// ---------------- host orchestration ----------------
extern "C" void kernel_launch(void* const* d_in, const int* in_sizes, int n_in,
                              void* d_out, int out_size) {
    const int* clusters;
    const float* features;
    if (in_sizes[0] == BB * PP) {
        clusters = (const int*)d_in[0];
        features = (const float*)d_in[1];
    } else {
        features = (const float*)d_in[0];
        clusters = (const int*)d_in[1];
    }
    const float* W1  = (const float*)d_in[2];
    const float* s1p = (const float*)d_in[3];
    const float* b1  = (const float*)d_in[4];
    const float* W2  = (const float*)d_in[5];
    const float* s2  = (const float*)d_in[6];
    const float* b2  = (const float*)d_in[7];
    const float* W3  = (const float*)d_in[8];
    const float* s3  = (const float*)d_in[9];
    const float* b3  = (const float*)d_in[10];
    const float* W4  = (const float*)d_in[11];
    const float* s4  = (const float*)d_in[12];
    const float* b4  = (const float*)d_in[13];
    const float* W5  = (const float*)d_in[14];
    const float* s5  = (const float*)d_in[15];
    const float* b5  = (const float*)d_in[16];
    const float* L1  = (const float*)d_in[17];
    const float* s6  = (const float*)d_in[18];
    const float* b6  = (const float*)d_in[19];
    const float* L2  = (const float*)d_in[20];
    const float* bl2 = (const float*)d_in[21];
    const float* s7  = (const float*)d_in[22];
    const float* b7  = (const float*)d_in[23];
    const float* L3  = (const float*)d_in[24];
    const float* bl3 = (const float*)d_in[25];
    float* out = (float*)d_out;

    static cudaStream_t s1s = nullptr;
    static cudaEvent_t evA, evW[4], evX[4];
    if (!s1s) {
        cudaFuncSetAttribute(mmagemm<EPI_PLAIN>, cudaFuncAttributeMaxDynamicSharedMemorySize, GEMM_SMEM);
        cudaFuncSetAttribute(mmagemm<EPI_POOL>,  cudaFuncAttributeMaxDynamicSharedMemorySize, GEMM_SMEM);
        cudaFuncSetAttribute(pdsym,              cudaFuncAttributeMaxDynamicSharedMemorySize, GEMM_SMEM);
        cudaStreamCreateWithFlags(&s1s, cudaStreamNonBlocking);
        cudaEventCreateWithFlags(&evA, cudaEventDisableTiming);
        for (int i = 0; i < 4; i++) {
            cudaEventCreateWithFlags(&evW[i], cudaEventDisableTiming);
            cudaEventCreateWithFlags(&evX[i], cudaEventDisableTiming);
        }
    }

    float *h0, *uw, *sq, *pmax, *psum;
    __nv_bfloat16 *h0h, *h0l, *xch, *xcl;
    __nv_bfloat16 *w1h, *w1l, *w2h, *w2l, *w3h, *w3l, *w4h, *w4l, *w5h, *w5l;
    cudaGetSymbolAddress((void**)&h0, g_h0);
    cudaGetSymbolAddress((void**)&uw, g_uw);
    cudaGetSymbolAddress((void**)&sq, g_sq);
    cudaGetSymbolAddress((void**)&pmax, g_pmax);
    cudaGetSymbolAddress((void**)&psum, g_psum);
    cudaGetSymbolAddress((void**)&h0h, g_h0h);
    cudaGetSymbolAddress((void**)&h0l, g_h0l);
    cudaGetSymbolAddress((void**)&xch, g_xch);
    cudaGetSymbolAddress((void**)&xcl, g_xcl);
    cudaGetSymbolAddress((void**)&w1h, g_w1h); cudaGetSymbolAddress((void**)&w1l, g_w1l);
    cudaGetSymbolAddress((void**)&w2h, g_w2h); cudaGetSymbolAddress((void**)&w2l, g_w2l);
    cudaGetSymbolAddress((void**)&w3h, g_w3h); cudaGetSymbolAddress((void**)&w3l, g_w3l);
    cudaGetSymbolAddress((void**)&w4h, g_w4h); cudaGetSymbolAddress((void**)&w4l, g_w4l);
    cudaGetSymbolAddress((void**)&w5h, g_w5h); cudaGetSymbolAddress((void**)&w5l, g_w5l);

    const __nv_bfloat16* hh[4] = { h0h, xch, xch, xch };
    const __nv_bfloat16* hl[4] = { h0l, xcl, xcl, xcl };
    int lda_s[4]   = { 128, 512, 512, 512 };
    int coff_s[4]  = { 0, 0, 64, 128 };
    int C_s[4]     = { 128, 64, 64, 128 };
    int O_s[4]     = { 64, 64, 128, 256 };
    const __nv_bfloat16* wh_s[4] = { w1h, w2h, w3h, w4h };
    const __nv_bfloat16* wl_s[4] = { w1l, w2l, w3l, w4l };
    const float* ss_s[4] = { s1p, s2, s3, s4 };
    const float* bb_s[4] = { b1, b2, b3, b4 };
    int ocoff_s[4] = { 0, 64, 128, 256 };

    prep_kernel<<<(8192 + 4096 + 8192 + 32768 + 262144 + 255) / 256, 256, 0, s1s>>>(W1, W2, W3, W4, W5);
    gather_kernel<<<(BB * PP * 32 + 255) / 256, 256>>>(features, clusters);
    sq_kernel<<<BB * PP / 8, 256>>>(h0, 128, 128);
    cudaEventRecord(evA, 0);
    cudaStreamWaitEvent(s1s, evA, 0);

    for (int st = 0; st < 4; st++) {
        long strideA = (long)PP * lda_s[st];

        // uw on side stream
        mmagemm<EPI_PLAIN><<<dim3((2 * O_s[st]) / 128, (BB * PP) / 128, 1), 256, GEMM_SMEM, s1s>>>(
            hh[st], hl[st], lda_s[st], 0, coff_s[st],
            wh_s[st], wl_s[st], C_s[st], 0, 0,
            uw, 2 * O_s[st], 0,
            C_s[st], nullptr, nullptr, nullptr, nullptr);
        cudaEventRecord(evW[st], s1s);

        // symmetric pd + topk on main stream
        pdsym<<<dim3(36, 1, BB), 256, GEMM_SMEM>>>(
            hh[st], hl[st], lda_s[st], strideA, coff_s[st], C_s[st]);
        topk_kernel<<<BB * PP / 8, 256>>>();

        cudaStreamWaitEvent(0, evW[st], 0);
        int G = 256 / O_s[st];
        agg_kernel<<<dim3(PP / G, BB), 256>>>(uw, ss_s[st], bb_s[st], O_s[st], ocoff_s[st], sq);
        if (st < 3) {
            cudaEventRecord(evX[st], 0);
            cudaStreamWaitEvent(s1s, evX[st], 0);
        }
    }

    // conv5 + BN + lrelu + fused partial pooling (no y5 materialization)
    mmagemm<EPI_POOL><<<dim3(4, (BB * PP) / 128, 1), 256, GEMM_SMEM>>>(
        xch, xcl, 512, 0, 0,
        w5h, w5l, 512, 0, 0,
        nullptr, 0, 0,
        512, s5, b5, pmax, psum);

    head_kernel<<<BB, 512>>>(L1, s6, b6, L2, bl2, s7, b7, L3, bl3, out);
}

// round 11
// speedup vs baseline: 1.7007x; 1.0509x over previous
#include <cuda_runtime.h>
#include <cuda_bf16.h>
#include <math.h>
#include <stdint.h>

#define BB 16
#define PP 1024
#define KNN 20
#define GB 8            // batches per group (2 groups)

// ---------------- scratch ----------------
__device__ float g_h0[BB * PP * 128];
__device__ __nv_bfloat16 g_h0h[BB * PP * 128];
__device__ __nv_bfloat16 g_h0l[BB * PP * 128];
__device__ __nv_bfloat16 g_xch[BB * PP * 512];
__device__ __nv_bfloat16 g_xcl[BB * PP * 512];
__device__ float g_uw[BB * PP * 512];              // partitioned: group g owns [g*GB*PP*512, ...)
__device__ float g_pd[BB * PP * PP];
__device__ int   g_knn[BB * PP * KNN];
__device__ float g_sq[BB * PP];
__device__ float g_pmax[BB * 8 * 512];
__device__ float g_psum[BB * 8 * 512];
__device__ __nv_bfloat16 g_w1h[128 * 128], g_w1l[128 * 128];
__device__ __nv_bfloat16 g_w2h[128 * 64],  g_w2l[128 * 64];
__device__ __nv_bfloat16 g_w3h[256 * 64],  g_w3l[256 * 64];
__device__ __nv_bfloat16 g_w4h[512 * 128], g_w4l[512 * 128];
__device__ __nv_bfloat16 g_w5h[512 * 512], g_w5l[512 * 512];

__device__ __forceinline__ void bsplit(float x, __nv_bfloat16& hi, __nv_bfloat16& lo) {
    hi = __float2bfloat16(x);
    lo = __float2bfloat16(x - __bfloat162float(hi));
}

__device__ __forceinline__ uint32_t smem_u32(const void* p) {
    uint32_t a;
    asm("{ .reg .u64 t; cvta.to.shared.u64 t, %1; cvt.u32.u64 %0, t; }" : "=r"(a) : "l"(p));
    return a;
}

__device__ __forceinline__ void cp_async16(uint32_t dst, const void* src) {
    asm volatile("cp.async.ca.shared.global [%0], [%1], 16;"
                 :: "r"(dst), "l"(__cvta_generic_to_global(src)));
}
#define CP_COMMIT() asm volatile("cp.async.commit_group;")

__device__ __forceinline__ void mma16816(float* c, const uint32_t* a, const uint32_t* b) {
    asm volatile(
        "mma.sync.aligned.m16n8k16.row.col.f32.bf16.bf16.f32 "
        "{%0,%1,%2,%3}, {%4,%5,%6,%7}, {%8,%9}, {%0,%1,%2,%3};"
        : "+f"(c[0]), "+f"(c[1]), "+f"(c[2]), "+f"(c[3])
        : "r"(a[0]), "r"(a[1]), "r"(a[2]), "r"(a[3]), "r"(b[0]), "r"(b[1]));
}

// ---------------- gather ----------------
__global__ void gather_kernel(const float* __restrict__ feats, const int* __restrict__ clusters) {
    int t = blockIdx.x * blockDim.x + threadIdx.x;
    if (t >= BB * PP * 32) return;
    int c4 = t & 31, bp = t >> 5;
    int src = clusters[bp];
    float4 v = reinterpret_cast<const float4*>(feats)[(size_t)src * 32 + c4];
    reinterpret_cast<float4*>(g_h0)[(size_t)bp * 32 + c4] = v;
    size_t e = (size_t)bp * 128 + c4 * 4;
    bsplit(v.x, g_h0h[e + 0], g_h0l[e + 0]);
    bsplit(v.y, g_h0h[e + 1], g_h0l[e + 1]);
    bsplit(v.z, g_h0h[e + 2], g_h0l[e + 2]);
    bsplit(v.w, g_h0h[e + 3], g_h0l[e + 3]);
}

// ---------------- squared norms (stage 1) ----------------
__global__ void sq_kernel(const float* __restrict__ h, int lda, int C) {
    int warp = (blockIdx.x * blockDim.x + threadIdx.x) >> 5;
    int lane = threadIdx.x & 31;
    if (warp >= BB * PP) return;
    const float* row = h + (size_t)warp * lda;
    float s = 0.f;
    for (int c = lane; c < C; c += 32) { float v = row[c]; s += v * v; }
    #pragma unroll
    for (int o = 16; o; o >>= 1) s += __shfl_xor_sync(0xffffffffu, s, o);
    if (lane == 0) g_sq[warp] = s;
}

// ---------------- merged weight prep ----------------
__global__ void prep_kernel(const float* __restrict__ W1, const float* __restrict__ W2,
                            const float* __restrict__ W3, const float* __restrict__ W4,
                            const float* __restrict__ W5) {
    int t = blockIdx.x * blockDim.x + threadIdx.x;
    if (t < 8192) {
        int o = t / 128, c = t % 128;
        float wa = W1[(size_t)o * 256 + c], wb = W1[(size_t)o * 256 + 128 + c];
        bsplit(wa, g_w1h[o * 128 + c], g_w1l[o * 128 + c]);
        bsplit(wb - wa, g_w1h[(64 + o) * 128 + c], g_w1l[(64 + o) * 128 + c]);
        return;
    }
    t -= 8192;
    if (t < 4096) {
        int o = t / 64, c = t % 64;
        float wa = W2[(size_t)o * 128 + c], wb = W2[(size_t)o * 128 + 64 + c];
        bsplit(wa, g_w2h[o * 64 + c], g_w2l[o * 64 + c]);
        bsplit(wb - wa, g_w2h[(64 + o) * 64 + c], g_w2l[(64 + o) * 64 + c]);
        return;
    }
    t -= 4096;
    if (t < 8192) {
        int o = t / 64, c = t % 64;
        float wa = W3[(size_t)o * 128 + c], wb = W3[(size_t)o * 128 + 64 + c];
        bsplit(wa, g_w3h[o * 64 + c], g_w3l[o * 64 + c]);
        bsplit(wb - wa, g_w3h[(128 + o) * 64 + c], g_w3l[(128 + o) * 64 + c]);
        return;
    }
    t -= 8192;
    if (t < 32768) {
        int o = t / 128, c = t % 128;
        float wa = W4[(size_t)o * 256 + c], wb = W4[(size_t)o * 256 + 128 + c];
        bsplit(wa, g_w4h[o * 128 + c], g_w4l[o * 128 + c]);
        bsplit(wb - wa, g_w4h[(256 + o) * 128 + c], g_w4l[(256 + o) * 128 + c]);
        return;
    }
    t -= 32768;
    if (t < 262144) {
        bsplit(W5[t], g_w5h[t], g_w5l[t]);
    }
}

// ---------------- shared GEMM pieces ----------------
#define EPI_PLAIN 0
#define EPI_POOL  2

#define STRIDE_W 20
#define TILE_BYTES (128 * STRIDE_W * 4)
#define GEMM_SMEM (2 * 4 * TILE_BYTES)

template<int EPI>
__global__ void __launch_bounds__(256)
mmagemm(const __nv_bfloat16* __restrict__ Ahi, const __nv_bfloat16* __restrict__ Alo,
        int lda, long sA, int acoff,
        const __nv_bfloat16* __restrict__ Bhi, const __nv_bfloat16* __restrict__ Blo,
        int ldb, long sB, int bcoff,
        float* __restrict__ Cout, int ldc, long sC,
        int K,
        const float* __restrict__ bn_s, const float* __restrict__ bn_b,
        float* __restrict__ pmax, float* __restrict__ psum) {
    extern __shared__ char dsm[];
    uint32_t smem_base = smem_u32(dsm);
    int tid = threadIdx.x;
    int lane = tid & 31, wid = tid >> 5;
    int warp_m = wid & 3, warp_n = wid >> 2;
    int g = lane >> 2, tid4 = lane & 3;
    int b = blockIdx.z;
    Ahi += (size_t)b * sA; Alo += (size_t)b * sA;
    Bhi += (size_t)b * sB; Blo += (size_t)b * sB;
    Cout += (size_t)b * sC;

    size_t aRow = (size_t)blockIdx.y * 128;
    size_t bRow = (size_t)blockIdx.x * 128;
    int nKb = K >> 5;

    float acc[2][8][4];
    #pragma unroll
    for (int mf = 0; mf < 2; mf++)
        #pragma unroll
        for (int nf = 0; nf < 8; nf++)
            #pragma unroll
            for (int i = 0; i < 4; i++) acc[mf][nf][i] = 0.f;

    auto load_block = [&](int buf, int kb) {
        uint32_t sbuf = smem_base + buf * 4 * TILE_BYTES;
        #pragma unroll
        for (int it = 0; it < 8; it++) {
            int i = tid + it * 256;
            int tile = i >> 9;
            int rem = i & 511;
            int row = rem >> 2;
            int chunk = rem & 3;
            uint32_t dst = sbuf + tile * TILE_BYTES + row * (STRIDE_W * 4) + chunk * 16;
            const __nv_bfloat16* src;
            if (tile == 0)      src = Ahi + (aRow + row) * lda + acoff + kb * 32 + chunk * 8;
            else if (tile == 1) src = Alo + (aRow + row) * lda + acoff + kb * 32 + chunk * 8;
            else if (tile == 2) src = Bhi + (bRow + row) * ldb + bcoff + kb * 32 + chunk * 8;
            else                src = Blo + (bRow + row) * ldb + bcoff + kb * 32 + chunk * 8;
            cp_async16(dst, src);
        }
        CP_COMMIT();
    };

    load_block(0, 0);
    int buf = 0;
    for (int kb = 0; kb < nKb; kb++) {
        bool pref = (kb + 1 < nKb);
        if (pref) load_block(buf ^ 1, kb + 1);
        if (pref) asm volatile("cp.async.wait_group 1;");
        else      asm volatile("cp.async.wait_group 0;");
        __syncthreads();

        const uint32_t* sAh = (const uint32_t*)(dsm + buf * 4 * TILE_BYTES);
        const uint32_t* sAl = sAh + (TILE_BYTES / 4);
        const uint32_t* sBh = sAh + 2 * (TILE_BYTES / 4);
        const uint32_t* sBl = sAh + 3 * (TILE_BYTES / 4);

        #pragma unroll
        for (int s = 0; s < 2; s++) {
            int pk0 = s * 8;
            uint32_t ah[2][4], al[2][4];
            #pragma unroll
            for (int mf = 0; mf < 2; mf++) {
                int R = warp_m * 32 + mf * 16;
                int base0 = (R + g) * STRIDE_W + pk0 + tid4;
                int base1 = (R + g + 8) * STRIDE_W + pk0 + tid4;
                ah[mf][0] = sAh[base0]; ah[mf][1] = sAh[base1];
                ah[mf][2] = sAh[base0 + 4]; ah[mf][3] = sAh[base1 + 4];
                al[mf][0] = sAl[base0]; al[mf][1] = sAl[base1];
                al[mf][2] = sAl[base0 + 4]; al[mf][3] = sAl[base1 + 4];
            }
            #pragma unroll
            for (int nf = 0; nf < 8; nf++) {
                int NR = warp_n * 64 + nf * 8 + g;
                int nb = NR * STRIDE_W + pk0 + tid4;
                uint32_t bh[2], bl[2];
                bh[0] = sBh[nb]; bh[1] = sBh[nb + 4];
                bl[0] = sBl[nb]; bl[1] = sBl[nb + 4];
                #pragma unroll
                for (int mf = 0; mf < 2; mf++) {
                    mma16816(acc[mf][nf], ah[mf], bh);
                    mma16816(acc[mf][nf], al[mf], bh);
                    mma16816(acc[mf][nf], ah[mf], bl);
                }
            }
        }
        __syncthreads();
        buf ^= 1;
    }

    if (EPI == EPI_POOL) {
        float tmax[16], tsum[16];
        #pragma unroll
        for (int j = 0; j < 16; j++) { tmax[j] = -INFINITY; tsum[j] = 0.f; }
        #pragma unroll
        for (int nf = 0; nf < 8; nf++) {
            int c = warp_n * 64 + nf * 8 + 2 * tid4;
            float2 cs = *reinterpret_cast<const float2*>(&bn_s[blockIdx.x * 128 + c]);
            float2 cb = *reinterpret_cast<const float2*>(&bn_b[blockIdx.x * 128 + c]);
            #pragma unroll
            for (int mf = 0; mf < 2; mf++) {
                float v0 = acc[mf][nf][0] * cs.x + cb.x; v0 = (v0 > 0.f) ? v0 : 0.2f * v0;
                float v1 = acc[mf][nf][1] * cs.y + cb.y; v1 = (v1 > 0.f) ? v1 : 0.2f * v1;
                float v2 = acc[mf][nf][2] * cs.x + cb.x; v2 = (v2 > 0.f) ? v2 : 0.2f * v2;
                float v3 = acc[mf][nf][3] * cs.y + cb.y; v3 = (v3 > 0.f) ? v3 : 0.2f * v3;
                tmax[nf * 2 + 0] = fmaxf(tmax[nf * 2 + 0], fmaxf(v0, v2));
                tmax[nf * 2 + 1] = fmaxf(tmax[nf * 2 + 1], fmaxf(v1, v3));
                tsum[nf * 2 + 0] += v0 + v2;
                tsum[nf * 2 + 1] += v1 + v3;
            }
        }
        #pragma unroll
        for (int off = 4; off <= 16; off <<= 1) {
            #pragma unroll
            for (int j = 0; j < 16; j++) {
                tmax[j] = fmaxf(tmax[j], __shfl_xor_sync(0xffffffffu, tmax[j], off));
                tsum[j] += __shfl_xor_sync(0xffffffffu, tsum[j], off);
            }
        }
        float* st = (float*)dsm;
        if (g == 0) {
            int base = ((warp_m * 2 + warp_n) * 4 + tid4) * 32;
            #pragma unroll
            for (int j = 0; j < 16; j++) { st[base + j] = tmax[j]; st[base + 16 + j] = tsum[j]; }
        }
        __syncthreads();
        if (warp_m == 0 && g == 0) {
            #pragma unroll
            for (int j = 0; j < 16; j++) {
                float m = -INFINITY, s = 0.f;
                #pragma unroll
                for (int wm = 0; wm < 4; wm++) {
                    int base = ((wm * 2 + warp_n) * 4 + tid4) * 32;
                    m = fmaxf(m, st[base + j]);
                    s += st[base + 16 + j];
                }
                int c = warp_n * 64 + (j >> 1) * 8 + 2 * tid4 + (j & 1);
                pmax[(size_t)blockIdx.y * 512 + blockIdx.x * 128 + c] = m;
                psum[(size_t)blockIdx.y * 512 + blockIdx.x * 128 + c] = s;
            }
        }
    } else {
        #pragma unroll
        for (int mf = 0; mf < 2; mf++) {
            size_t r0 = aRow + warp_m * 32 + mf * 16 + g;
            size_t r1 = r0 + 8;
            #pragma unroll
            for (int nf = 0; nf < 8; nf++) {
                size_t c = (size_t)blockIdx.x * 128 + warp_n * 64 + nf * 8 + 2 * tid4;
                *reinterpret_cast<float2*>(&Cout[r0 * ldc + c]) = make_float2(acc[mf][nf][0], acc[mf][nf][1]);
                *reinterpret_cast<float2*>(&Cout[r1 * ldc + c]) = make_float2(acc[mf][nf][2], acc[mf][nf][3]);
            }
        }
    }
}

// ---------------- symmetric pd GEMM (lower triangle + mirrored write) ----------------
__global__ void __launch_bounds__(256)
pdsym(const __nv_bfloat16* __restrict__ Ahi, const __nv_bfloat16* __restrict__ Alo,
      int lda, long sA, int acoff, int K, int bbase) {
    extern __shared__ char dsm[];
    uint32_t smem_base = smem_u32(dsm);
    int tid = threadIdx.x;
    int lane = tid & 31, wid = tid >> 5;
    int warp_m = wid & 3, warp_n = wid >> 2;
    int g = lane >> 2, tid4 = lane & 3;
    int b = bbase + blockIdx.z;
    const __nv_bfloat16* Hh = Ahi + (size_t)b * sA;
    const __nv_bfloat16* Hl = Alo + (size_t)b * sA;
    float* pd = g_pd + (size_t)b * PP * PP;
    const float* sqb = g_sq + (size_t)b * PP;

    int t36 = blockIdx.x, by = 0;
    while (t36 > by) { t36 -= by + 1; by++; }
    int bx = t36;

    size_t aRow = (size_t)by * 128;
    size_t bRow = (size_t)bx * 128;
    int nKb = K >> 5;

    float acc[2][8][4];
    #pragma unroll
    for (int mf = 0; mf < 2; mf++)
        #pragma unroll
        for (int nf = 0; nf < 8; nf++)
            #pragma unroll
            for (int i = 0; i < 4; i++) acc[mf][nf][i] = 0.f;

    auto load_block = [&](int buf, int kb) {
        uint32_t sbuf = smem_base + buf * 4 * TILE_BYTES;
        #pragma unroll
        for (int it = 0; it < 8; it++) {
            int i = tid + it * 256;
            int tile = i >> 9;
            int rem = i & 511;
            int row = rem >> 2;
            int chunk = rem & 3;
            uint32_t dst = sbuf + tile * TILE_BYTES + row * (STRIDE_W * 4) + chunk * 16;
            const __nv_bfloat16* src;
            if (tile == 0)      src = Hh + (aRow + row) * lda + acoff + kb * 32 + chunk * 8;
            else if (tile == 1) src = Hl + (aRow + row) * lda + acoff + kb * 32 + chunk * 8;
            else if (tile == 2) src = Hh + (bRow + row) * lda + acoff + kb * 32 + chunk * 8;
            else                src = Hl + (bRow + row) * lda + acoff + kb * 32 + chunk * 8;
            cp_async16(dst, src);
        }
        CP_COMMIT();
    };

    load_block(0, 0);
    int buf = 0;
    for (int kb = 0; kb < nKb; kb++) {
        bool pref = (kb + 1 < nKb);
        if (pref) load_block(buf ^ 1, kb + 1);
        if (pref) asm volatile("cp.async.wait_group 1;");
        else      asm volatile("cp.async.wait_group 0;");
        __syncthreads();

        const uint32_t* sAh = (const uint32_t*)(dsm + buf * 4 * TILE_BYTES);
        const uint32_t* sAl = sAh + (TILE_BYTES / 4);
        const uint32_t* sBh = sAh + 2 * (TILE_BYTES / 4);
        const uint32_t* sBl = sAh + 3 * (TILE_BYTES / 4);

        #pragma unroll
        for (int s = 0; s < 2; s++) {
            int pk0 = s * 8;
            uint32_t ah[2][4], al[2][4];
            #pragma unroll
            for (int mf = 0; mf < 2; mf++) {
                int R = warp_m * 32 + mf * 16;
                int base0 = (R + g) * STRIDE_W + pk0 + tid4;
                int base1 = (R + g + 8) * STRIDE_W + pk0 + tid4;
                ah[mf][0] = sAh[base0]; ah[mf][1] = sAh[base1];
                ah[mf][2] = sAh[base0 + 4]; ah[mf][3] = sAh[base1 + 4];
                al[mf][0] = sAl[base0]; al[mf][1] = sAl[base1];
                al[mf][2] = sAl[base0 + 4]; al[mf][3] = sAl[base1 + 4];
            }
            #pragma unroll
            for (int nf = 0; nf < 8; nf++) {
                int NR = warp_n * 64 + nf * 8 + g;
                int nb = NR * STRIDE_W + pk0 + tid4;
                uint32_t bh[2], bl[2];
                bh[0] = sBh[nb]; bh[1] = sBh[nb + 4];
                bl[0] = sBl[nb]; bl[1] = sBl[nb + 4];
                #pragma unroll
                for (int mf = 0; mf < 2; mf++) {
                    mma16816(acc[mf][nf], ah[mf], bh);
                    mma16816(acc[mf][nf], al[mf], bh);
                    mma16816(acc[mf][nf], ah[mf], bl);
                }
            }
        }
        __syncthreads();
        buf ^= 1;
    }

    #pragma unroll
    for (int mf = 0; mf < 2; mf++) {
        size_t r0 = aRow + warp_m * 32 + mf * 16 + g;
        size_t r1 = r0 + 8;
        #pragma unroll
        for (int nf = 0; nf < 8; nf++) {
            size_t c = bRow + warp_n * 64 + nf * 8 + 2 * tid4;
            float2 cs = *reinterpret_cast<const float2*>(&sqb[c]);
            *reinterpret_cast<float2*>(&pd[r0 * PP + c]) =
                make_float2(2.f * acc[mf][nf][0] - cs.x, 2.f * acc[mf][nf][1] - cs.y);
            *reinterpret_cast<float2*>(&pd[r1 * PP + c]) =
                make_float2(2.f * acc[mf][nf][2] - cs.x, 2.f * acc[mf][nf][3] - cs.y);
        }
    }

    if (bx != by) {
        float* st = (float*)dsm;
        #pragma unroll
        for (int mf = 0; mf < 2; mf++) {
            int rl0 = warp_m * 32 + mf * 16 + g;
            int rl1 = rl0 + 8;
            #pragma unroll
            for (int nf = 0; nf < 8; nf++) {
                int cl = warp_n * 64 + nf * 8 + 2 * tid4;
                st[rl0 * 129 + cl]     = 2.f * acc[mf][nf][0];
                st[rl0 * 129 + cl + 1] = 2.f * acc[mf][nf][1];
                st[rl1 * 129 + cl]     = 2.f * acc[mf][nf][2];
                st[rl1 * 129 + cl + 1] = 2.f * acc[mf][nf][3];
            }
        }
        __syncthreads();
        for (int i = tid; i < 128 * 32; i += 256) {
            int cl = i >> 5;
            int r  = (i & 31) * 4;
            float4 sv;
            sv.x = st[(r + 0) * 129 + cl];
            sv.y = st[(r + 1) * 129 + cl];
            sv.z = st[(r + 2) * 129 + cl];
            sv.w = st[(r + 3) * 129 + cl];
            float4 sq4 = *reinterpret_cast<const float4*>(&sqb[aRow + r]);
            float4 o = make_float4(sv.x - sq4.x, sv.y - sq4.y, sv.z - sq4.z, sv.w - sq4.w);
            *reinterpret_cast<float4*>(&pd[(bRow + cl) * PP + aRow + r]) = o;
        }
    }
}

// ---------------- top-20 per row: register-resident ----------------
__global__ void __launch_bounds__(256) topk_kernel(int rowbase) {
    int warp = threadIdx.x >> 5, lane = threadIdx.x & 31;
    int row = rowbase + blockIdx.x * 8 + warp;
    const float* __restrict__ prow = g_pd + (size_t)row * PP;

    float v[32];
    #pragma unroll
    for (int slot = 0; slot < 32; slot++) v[slot] = __ldg(&prow[slot * 32 + lane]);

    float m1 = -INFINITY, m2 = -INFINITY;
    int i1 = PP, i2 = PP;
    #pragma unroll
    for (int slot = 0; slot < 32; slot++) {
        float x = v[slot];
        int j = slot * 32 + lane;
        if (x > m1) { m2 = m1; i2 = i1; m1 = x; i1 = j; }
        else if (x > m2) { m2 = x; i2 = j; }
    }
    bool have2 = true;
    unsigned mask = 0;

    for (int k = 0; k < KNN; k++) {
        float best = m1; int bi = i1;
        #pragma unroll
        for (int o = 16; o; o >>= 1) {
            float ov = __shfl_xor_sync(0xffffffffu, best, o);
            int   oi = __shfl_xor_sync(0xffffffffu, bi, o);
            if (ov > best || (ov == best && oi < bi)) { best = ov; bi = oi; }
        }
        if (lane == 0) g_knn[row * KNN + k] = bi;
        if (i1 == bi) {
            mask |= 1u << (bi >> 5);
            if (have2) { m1 = m2; i1 = i2; have2 = false; }
            else {
                m1 = -INFINITY; m2 = -INFINITY; i1 = PP; i2 = PP;
                #pragma unroll
                for (int slot = 0; slot < 32; slot++) {
                    if (!(mask & (1u << slot))) {
                        float x = v[slot];
                        int j = slot * 32 + lane;
                        if (x > m1) { m2 = m1; i2 = i1; m1 = x; i1 = j; }
                        else if (x > m2) { m2 = x; i2 = j; }
                    }
                }
                have2 = true;
            }
        }
    }
}

// ---------------- aggregate + fused next-stage sq + bf16 split output ----------------
// uw points at the GROUP's slab; rows indexed locally by (blockIdx.y, p).
__global__ void __launch_bounds__(256) agg_kernel(
    const float* __restrict__ uw,
    const float* __restrict__ s, const float* __restrict__ bias,
    int O, int coloff, float* __restrict__ sqout, int bbase) {
    __shared__ int sidx[128];
    __shared__ float red[256];
    int tid = threadIdx.x;
    int G = 256 / O;
    int pi = tid / O;
    int o = tid - pi * O;
    int bl = blockIdx.y;            // local batch within group
    int b = bbase + bl;             // global batch
    int p = blockIdx.x * G + pi;
    size_t base = (size_t)b * PP + p;

    if (tid < G * KNN) {
        int gp = tid / KNN, kk = tid - gp * KNN;
        sidx[tid] = g_knn[((size_t)b * PP + blockIdx.x * G + gp) * KNN + kk];
    }
    __syncthreads();

    int twoO = 2 * O;
    const float* __restrict__ ub = uw + (size_t)bl * PP * twoO;   // LOCAL index into group slab
    float wv = __ldg(&ub[(size_t)p * twoO + O + o]);
    float sv = s[o], bv = bias[o];
    const int* idx = sidx + pi * KNN;
    float m = -INFINITY;
    #pragma unroll
    for (int k = 0; k < KNN; k++) {
        int nb = idx[k];
        float y = __ldg(&ub[(size_t)nb * twoO + o]) + wv;
        y = y * sv + bv;
        y = (y > 0.f) ? y : 0.2f * y;
        m = fmaxf(m, y);
    }
    bsplit(m, g_xch[base * 512 + coloff + o], g_xcl[base * 512 + coloff + o]);

    red[tid] = m * m;
    __syncthreads();
    for (int st = O >> 1; st > 0; st >>= 1) {
        if (o < st) red[tid] += red[tid + st];
        __syncthreads();
    }
    if (o == 0) sqout[base] = red[tid];
}

// ---------------- MLP head (with inline pool combine) ----------------
__global__ void head_kernel(const float* __restrict__ L1, const float* __restrict__ s6, const float* __restrict__ b6,
                            const float* __restrict__ L2, const float* __restrict__ bl2,
                            const float* __restrict__ s7, const float* __restrict__ b7,
                            const float* __restrict__ L3, const float* __restrict__ bl3,
                            float* __restrict__ out) {
    __shared__ float sf[1024];
    __shared__ float z1[512];
    __shared__ float z2[256];
    int b = blockIdx.x, t = threadIdx.x;
    {
        float mx = -INFINITY, sm = 0.f;
        #pragma unroll
        for (int c = 0; c < 8; c++) {
            mx = fmaxf(mx, g_pmax[(b * 8 + c) * 512 + t]);
            sm += g_psum[(b * 8 + c) * 512 + t];
        }
        sf[t] = mx;
        sf[t + 512] = sm * (1.0f / PP);
    }
    __syncthreads();
    {
        float a = 0.f;
        const float* r = L1 + (size_t)t * 1024;
        for (int j = 0; j < 1024; j++) a += sf[j] * r[j];
        a = a * s6[t] + b6[t];
        z1[t] = (a > 0.f) ? a : 0.2f * a;
    }
    __syncthreads();
    if (t < 256) {
        float a = 0.f;
        const float* r = L2 + (size_t)t * 512;
        for (int j = 0; j < 512; j++) a += z1[j] * r[j];
        a = (a + bl2[t]) * s7[t] + b7[t];
        a = (a > 0.f) ? a : 0.2f * a;
        z2[t] = a * L3[t];
    }
    __syncthreads();
    if (t < 128) z2[t] += z2[t + 128];
    __syncthreads();
    if (t < 64) z2[t] += z2[t + 64];
    __syncthreads();
    if (t < 32) {
        float v = z2[t] + z2[t + 32];
        #pragma unroll
        for (int o = 16; o; o >>= 1) v += __shfl_down_sync(0xffffffffu, v, o);
        if (t == 0) {
            float z = v + bl3[0];
            out[b] = 1.0f / (1.0f + expf(-z));
        }
    }
}

// ---------------- host orchestration ----------------
extern "C" void kernel_launch(void* const* d_in, const int* in_sizes, int n_in,
                              void* d_out, int out_size) {
    const int* clusters;
    const float* features;
    if (in_sizes[0] == BB * PP) {
        clusters = (const int*)d_in[0];
        features = (const float*)d_in[1];
    } else {
        features = (const float*)d_in[0];
        clusters = (const int*)d_in[1];
    }
    const float* W1  = (const float*)d_in[2];
    const float* s1p = (const float*)d_in[3];
    const float* b1  = (const float*)d_in[4];
    const float* W2  = (const float*)d_in[5];
    const float* s2  = (const float*)d_in[6];
    const float* b2  = (const float*)d_in[7];
    const float* W3  = (const float*)d_in[8];
    const float* s3  = (const float*)d_in[9];
    const float* b3  = (const float*)d_in[10];
    const float* W4  = (const float*)d_in[11];
    const float* s4  = (const float*)d_in[12];
    const float* b4  = (const float*)d_in[13];
    const float* W5  = (const float*)d_in[14];
    const float* s5  = (const float*)d_in[15];
    const float* b5  = (const float*)d_in[16];
    const float* L1  = (const float*)d_in[17];
    const float* s6  = (const float*)d_in[18];
    const float* b6  = (const float*)d_in[19];
    const float* L2  = (const float*)d_in[20];
    const float* bl2 = (const float*)d_in[21];
    const float* s7  = (const float*)d_in[22];
    const float* b7  = (const float*)d_in[23];
    const float* L3  = (const float*)d_in[24];
    const float* bl3 = (const float*)d_in[25];
    float* out = (float*)d_out;

    static cudaStream_t s1s = nullptr;
    static cudaEvent_t evRoot, evA, evP, evG1;
    if (!s1s) {
        cudaFuncSetAttribute(mmagemm<EPI_PLAIN>, cudaFuncAttributeMaxDynamicSharedMemorySize, GEMM_SMEM);
        cudaFuncSetAttribute(mmagemm<EPI_POOL>,  cudaFuncAttributeMaxDynamicSharedMemorySize, GEMM_SMEM);
        cudaFuncSetAttribute(pdsym,              cudaFuncAttributeMaxDynamicSharedMemorySize, GEMM_SMEM);
        cudaStreamCreateWithFlags(&s1s, cudaStreamNonBlocking);
        cudaEventCreateWithFlags(&evRoot, cudaEventDisableTiming);
        cudaEventCreateWithFlags(&evA, cudaEventDisableTiming);
        cudaEventCreateWithFlags(&evP, cudaEventDisableTiming);
        cudaEventCreateWithFlags(&evG1, cudaEventDisableTiming);
    }

    float *h0, *uw, *sq, *pmax, *psum;
    __nv_bfloat16 *h0h, *h0l, *xch, *xcl;
    __nv_bfloat16 *w1h, *w1l, *w2h, *w2l, *w3h, *w3l, *w4h, *w4l, *w5h, *w5l;
    cudaGetSymbolAddress((void**)&h0, g_h0);
    cudaGetSymbolAddress((void**)&uw, g_uw);
    cudaGetSymbolAddress((void**)&sq, g_sq);
    cudaGetSymbolAddress((void**)&pmax, g_pmax);
    cudaGetSymbolAddress((void**)&psum, g_psum);
    cudaGetSymbolAddress((void**)&h0h, g_h0h);
    cudaGetSymbolAddress((void**)&h0l, g_h0l);
    cudaGetSymbolAddress((void**)&xch, g_xch);
    cudaGetSymbolAddress((void**)&xcl, g_xcl);
    cudaGetSymbolAddress((void**)&w1h, g_w1h); cudaGetSymbolAddress((void**)&w1l, g_w1l);
    cudaGetSymbolAddress((void**)&w2h, g_w2h); cudaGetSymbolAddress((void**)&w2l, g_w2l);
    cudaGetSymbolAddress((void**)&w3h, g_w3h); cudaGetSymbolAddress((void**)&w3l, g_w3l);
    cudaGetSymbolAddress((void**)&w4h, g_w4h); cudaGetSymbolAddress((void**)&w4l, g_w4l);
    cudaGetSymbolAddress((void**)&w5h, g_w5h); cudaGetSymbolAddress((void**)&w5l, g_w5l);

    const __nv_bfloat16* hh[4] = { h0h, xch, xch, xch };
    const __nv_bfloat16* hl[4] = { h0l, xcl, xcl, xcl };
    int lda_s[4]   = { 128, 512, 512, 512 };
    int coff_s[4]  = { 0, 0, 64, 128 };
    int C_s[4]     = { 128, 64, 64, 128 };
    int O_s[4]     = { 64, 64, 128, 256 };
    const __nv_bfloat16* wh_s[4] = { w1h, w2h, w3h, w4h };
    const __nv_bfloat16* wl_s[4] = { w1l, w2l, w3l, w4l };
    const float* ss_s[4] = { s1p, s2, s3, s4 };
    const float* bb_s[4] = { b1, b2, b3, b4 };
    int ocoff_s[4] = { 0, 64, 128, 256 };

    // fork: prep on side stream
    cudaEventRecord(evRoot, 0);
    cudaStreamWaitEvent(s1s, evRoot, 0);
    prep_kernel<<<(8192 + 4096 + 8192 + 32768 + 262144 + 255) / 256, 256, 0, s1s>>>(W1, W2, W3, W4, W5);
    cudaEventRecord(evP, s1s);

    gather_kernel<<<(BB * PP * 32 + 255) / 256, 256>>>(features, clusters);
    sq_kernel<<<BB * PP / 8, 256>>>(h0, 128, 128);
    cudaEventRecord(evA, 0);

    // group 0 (batches 0..7) on main stream; group 1 (batches 8..15) on side stream
    cudaStreamWaitEvent(0, evP, 0);
    cudaStreamWaitEvent(s1s, evA, 0);

    cudaStream_t streams[2] = { 0, s1s };
    for (int grp = 0; grp < 2; grp++) {
        cudaStream_t st = streams[grp];
        int bbase = grp * GB;
        float* uwg = uw + (size_t)grp * GB * PP * 512;   // fixed stage-independent group slab

        for (int s = 0; s < 4; s++) {
            long strideA = (long)PP * lda_s[s];
            int C = C_s[s], O = O_s[s];
            size_t hoff = (size_t)bbase * PP * lda_s[s];

            mmagemm<EPI_PLAIN><<<dim3((2 * O) / 128, (GB * PP) / 128, 1), 256, GEMM_SMEM, st>>>(
                hh[s] + hoff, hl[s] + hoff, lda_s[s], 0, coff_s[s],
                wh_s[s], wl_s[s], C, 0, 0,
                uwg, 2 * O, 0,
                C, nullptr, nullptr, nullptr, nullptr);

            pdsym<<<dim3(36, 1, GB), 256, GEMM_SMEM, st>>>(
                hh[s], hl[s], lda_s[s], strideA, coff_s[s], C, bbase);

            topk_kernel<<<GB * PP / 8, 256, 0, st>>>(bbase * PP);

            int Gp = 256 / O;
            agg_kernel<<<dim3(PP / Gp, GB), 256, 0, st>>>(
                uwg, ss_s[s], bb_s[s], O, ocoff_s[s], sq, bbase);
        }

        mmagemm<EPI_POOL><<<dim3(4, (GB * PP) / 128, 1), 256, GEMM_SMEM, st>>>(
            xch + (size_t)bbase * PP * 512, xcl + (size_t)bbase * PP * 512, 512, 0, 0,
            w5h, w5l, 512, 0, 0,
            nullptr, 0, 0,
            512, s5, b5, pmax + (size_t)bbase * 8 * 512, psum + (size_t)bbase * 8 * 512);
    }

    cudaEventRecord(evG1, s1s);
    cudaStreamWaitEvent(0, evG1, 0);
    head_kernel<<<BB, 512>>>(L1, s6, b6, L2, bl2, s7, b7, L3, bl3, out);
}